// round 3
// baseline (speedup 1.0000x reference)
#include <cuda_runtime.h>
#include <math.h>
#include <stdint.h>

// Problem constants (B=1)
#define H_   8
#define S_   1024
#define D_   64
#define KG_  10

// Tiling
#define BI   64
#define BJ   64
#define NT   256
#define NSPLIT 2
#define TILES_PER_SPLIT (S_ / BJ / NSPLIT)

// LUT
#define LUTN    2048
#define RANGE_D 10.0f
#define RANGE_E 5.0f

// smem strides (padded)
#define QSTR 68   // transposed Q/K tiles: [D][BI+4]
#define PSTR 68   // P tile: [BI][BJ+4]

__device__ float2 g_lutD[LUTN];
__device__ float2 g_lutE[LUTN];
__device__ float  g_vals[2][LUTN + 1];
// split-KV scratch (static __device__: no allocation)
__device__ float  g_Opart[NSPLIT][H_ * S_ * D_];
__device__ float2 g_ML[NSPLIT][H_ * S_];

// ---------------------------------------------------------------------------
// Packed fp32x2 helpers (Blackwell FFMA2 — only reachable via PTX)
// ---------------------------------------------------------------------------
typedef unsigned long long f32x2_t;
__device__ __forceinline__ f32x2_t pack2(float lo, float hi) {
    f32x2_t r; asm("mov.b64 %0, {%1, %2};" : "=l"(r) : "f"(lo), "f"(hi)); return r;
}
__device__ __forceinline__ f32x2_t splat2(float x) { return pack2(x, x); }
__device__ __forceinline__ void fma2(f32x2_t& d, f32x2_t a, f32x2_t b) {
    asm("fma.rn.f32x2 %0, %1, %2, %0;" : "+l"(d) : "l"(a), "l"(b));
}
__device__ __forceinline__ void scale2(f32x2_t& d, f32x2_t s) {
    asm("mul.rn.f32x2 %0, %0, %1;" : "+l"(d) : "l"(s));
}
__device__ __forceinline__ void unpack2(float& lo, float& hi, f32x2_t v) {
    asm("mov.b64 {%0, %1}, %2;" : "=f"(lo), "=f"(hi) : "l"(v));
}

// ---------------------------------------------------------------------------
// LUT construction: full RBF -> MLP(exact GELU) bias, one eval per thread.
// ---------------------------------------------------------------------------
__device__ __forceinline__ float gelu_exact(float x) {
    return 0.5f * x * (1.0f + erff(x * 0.70710678118654752f));
}

__device__ float bias_eval(float x,
                           const float* __restrict__ mu, const float* __restrict__ sg,
                           const float* __restrict__ bb,
                           const float* __restrict__ W1, const float* __restrict__ b1,
                           const float* __restrict__ W2, float b2v) {
    float psi[KG_];
#pragma unroll
    for (int k = 0; k < KG_; k++) {
        float s = sg[k];
        float z = (x + bb[k] - mu[k]) / s;
        psi[k] = expf(-0.5f * z * z) * (0.3989422804014327f / s);
    }
    float acc = b2v;
#pragma unroll
    for (int l = 0; l < KG_; l++) {
        float hv = b1[l];
#pragma unroll
        for (int k = 0; k < KG_; k++) hv = fmaf(W1[l * KG_ + k], psi[k], hv);
        acc = fmaf(W2[l], gelu_exact(hv), acc);
    }
    return acc;
}

__global__ void build_vals_kernel(const float* __restrict__ muD, const float* __restrict__ sgD,
                                  const float* __restrict__ bD,
                                  const float* __restrict__ muE, const float* __restrict__ sgE,
                                  const float* __restrict__ bE,
                                  const float* __restrict__ W1, const float* __restrict__ b1,
                                  const float* __restrict__ W2, const float* __restrict__ b2) {
    int idx = blockIdx.x * blockDim.x + threadIdx.x;
    if (idx >= 2 * (LUTN + 1)) return;
    int which = idx / (LUTN + 1);
    int i = idx % (LUTN + 1);
    float b2v = b2[0];
    if (which == 0) {
        g_vals[0][i] = bias_eval((float)i * (RANGE_D / (float)LUTN), muD, sgD, bD, W1, b1, W2, b2v);
    } else {
        g_vals[1][i] = bias_eval((float)i * (RANGE_E / (float)LUTN), muE, sgE, bE, W1, b1, W2, b2v);
    }
}

__global__ void build_slopes_kernel() {
    int i = blockIdx.x * blockDim.x + threadIdx.x;
    if (i >= LUTN) return;
    float d0 = g_vals[0][i];
    g_lutD[i] = make_float2(d0, g_vals[0][i + 1] - d0);
    float e0 = g_vals[1][i];
    g_lutE[i] = make_float2(e0, g_vals[1][i + 1] - e0);
}

// ---------------------------------------------------------------------------
// Fused flash attention with LUT biases. Split-KV partial kernel.
// grid = (S/BI, H, NSPLIT), block = 256 (16x16 thread grid, 4x4 micro-tile).
// ---------------------------------------------------------------------------
__device__ __forceinline__ float lut_interp(const float2* __restrict__ lut, float x, float scale) {
    float t = x * scale;
    int ix = (int)t;
    ix = max(0, min(ix, LUTN - 1));
    float f = t - (float)ix;
    float2 e = lut[ix];
    return fmaf(e.y, f, e.x);
}

__device__ __forceinline__ void ldg_kv(const float* __restrict__ Kbase,
                                       const float* __restrict__ Vbase,
                                       int tid, float4* kk, float4* vv) {
#pragma unroll
    for (int k = 0; k < 4; k++) {
        int fi = tid + k * NT;
        int row = fi >> 4;
        int dcol = (fi & 15) * 4;
        kk[k] = *(const float4*)(Kbase + row * D_ + dcol);
        vv[k] = *(const float4*)(Vbase + fi * 4);
    }
}

__global__ __launch_bounds__(NT, 2) void attn_partial_kernel(
    const float* __restrict__ Qg, const float* __restrict__ Kg, const float* __restrict__ Vg,
    const float* __restrict__ DMg, const float* __restrict__ EMg, const int* __restrict__ Mg) {
    extern __shared__ unsigned char smraw[];
    float2* lutD = (float2*)smraw;
    float2* lutE = lutD + LUTN;
    float* Qs = (float*)(lutE + LUTN);   // [D][QSTR] transposed
    float* Ks = Qs + D_ * QSTR;          // [D][QSTR] transposed
    float* Vs = Ks + D_ * QSTR;          // [BJ][D]
    float* Ps = Vs + BJ * D_;            // [BI][PSTR]

    const int tid = threadIdx.x;
    const int h = blockIdx.y;
    const int i0 = blockIdx.x * BI;
    const int split = blockIdx.z;
    const int tr = tid >> 4;   // 0..15: query-row group
    const int tc = tid & 15;   // 0..15: col group

    const float lscaleD = (float)LUTN / RANGE_D;
    const float lscaleE = (float)LUTN / RANGE_E;

    // Stage LUTs into shared (coalesced)
    for (int t = tid; t < LUTN; t += NT) lutD[t] = g_lutD[t];
    for (int t = tid; t < LUTN; t += NT) lutE[t] = g_lutE[t];

    // Load Q tile transposed: Qs[d][i]
    const float* Qbase = Qg + ((size_t)h * S_ + i0) * D_;
#pragma unroll
    for (int k = 0; k < (BI * D_ / 4) / NT; k++) {
        int fi = tid + k * NT;          // 0..1023
        int row = fi >> 4;              // 16 float4 per row
        int dcol = (fi & 15) * 4;
        float4 q = *(const float4*)(Qbase + row * D_ + dcol);
        Qs[(dcol + 0) * QSTR + row] = q.x;
        Qs[(dcol + 1) * QSTR + row] = q.y;
        Qs[(dcol + 2) * QSTR + row] = q.z;
        Qs[(dcol + 3) * QSTR + row] = q.w;
    }

    f32x2_t o2[4][2];
    float mrow[4], lrow[4];
#pragma unroll
    for (int r = 0; r < 4; r++) {
        mrow[r] = -1e30f;
        lrow[r] = 0.f;
        o2[r][0] = 0ull;
        o2[r][1] = 0ull;
    }

    const float qk_scale = 0.0883883476483184f;  // 1/sqrt(2*D)

    const float* Kh = Kg + (size_t)h * S_ * D_;
    const float* Vh = Vg + (size_t)h * S_ * D_;

    // Prefetch tile 0 K/V into registers
    float4 kk[4], vv[4];
    {
        int j0 = split * TILES_PER_SPLIT * BJ;
        ldg_kv(Kh + (size_t)j0 * D_, Vh + (size_t)j0 * D_, tid, kk, vv);
    }

    for (int jt = 0; jt < TILES_PER_SPLIT; jt++) {
        const int j0 = (split * TILES_PER_SPLIT + jt) * BJ;

        // Early-issue global loads for bias matrices + mask (hidden under QK)
        float4 dm[4], em[4];
        int4 mk[4];
#pragma unroll
        for (int r = 0; r < 4; r++) {
            int ig = i0 + tr * 4 + r;
            size_t base = ((size_t)h * S_ + ig) * S_ + j0 + tc * 4;
            dm[r] = *(const float4*)(DMg + base);
            em[r] = *(const float4*)(EMg + base);
            mk[r] = *(const int4*)(Mg + base);
        }

        __syncthreads();  // prev-iter K/V/P consumers done

        // Store prefetched K (transposed) and V tiles to smem
#pragma unroll
        for (int k = 0; k < 4; k++) {
            int fi = tid + k * NT;
            int row = fi >> 4;
            int dcol = (fi & 15) * 4;
            Ks[(dcol + 0) * QSTR + row] = kk[k].x;
            Ks[(dcol + 1) * QSTR + row] = kk[k].y;
            Ks[(dcol + 2) * QSTR + row] = kk[k].z;
            Ks[(dcol + 3) * QSTR + row] = kk[k].w;
            *(float4*)(Vs + fi * 4) = vv[k];
        }

        __syncthreads();  // tiles visible

        // QK^T: 4x4 micro-tile per thread, packed f32x2 (FFMA2)
        f32x2_t sc2[4][2];
#pragma unroll
        for (int r = 0; r < 4; r++) { sc2[r][0] = 0ull; sc2[r][1] = 0ull; }

#pragma unroll 8
        for (int k = 0; k < D_; k++) {
            float4 a = *(const float4*)(Qs + k * QSTR + tr * 4);
            float4 b = *(const float4*)(Ks + k * QSTR + tc * 4);
            f32x2_t b01 = pack2(b.x, b.y);
            f32x2_t b23 = pack2(b.z, b.w);
            float av[4] = {a.x, a.y, a.z, a.w};
#pragma unroll
            for (int r = 0; r < 4; r++) {
                f32x2_t aa = splat2(av[r]);
                fma2(sc2[r][0], aa, b01);
                fma2(sc2[r][1], aa, b23);
            }
        }

        // unpack, scale + LUT biases + mask
        float sc[4][4];
#pragma unroll
        for (int r = 0; r < 4; r++) {
            unpack2(sc[r][0], sc[r][1], sc2[r][0]);
            unpack2(sc[r][2], sc[r][3], sc2[r][1]);
            const float* dp = (const float*)&dm[r];
            const float* ep = (const float*)&em[r];
            const int* mp = (const int*)&mk[r];
#pragma unroll
            for (int c = 0; c < 4; c++) {
                float s = sc[r][c] * qk_scale
                        + lut_interp(lutD, dp[c], lscaleD)
                        + lut_interp(lutE, ep[c], lscaleE);
                sc[r][c] = (mp[c] == 0) ? -1e9f : s;
            }
        }

        // Online softmax over this tile (row reduce across 16 lanes)
#pragma unroll
        for (int r = 0; r < 4; r++) {
            float mx = fmaxf(fmaxf(sc[r][0], sc[r][1]), fmaxf(sc[r][2], sc[r][3]));
            mx = fmaxf(mx, __shfl_xor_sync(0xffffffffu, mx, 8));
            mx = fmaxf(mx, __shfl_xor_sync(0xffffffffu, mx, 4));
            mx = fmaxf(mx, __shfl_xor_sync(0xffffffffu, mx, 2));
            mx = fmaxf(mx, __shfl_xor_sync(0xffffffffu, mx, 1));
            float mnew = fmaxf(mrow[r], mx);
            float corr = __expf(mrow[r] - mnew);
            mrow[r] = mnew;
            float ps = 0.f;
#pragma unroll
            for (int c = 0; c < 4; c++) {
                float p = __expf(sc[r][c] - mnew);
                sc[r][c] = p;
                ps += p;
            }
            ps += __shfl_xor_sync(0xffffffffu, ps, 8);
            ps += __shfl_xor_sync(0xffffffffu, ps, 4);
            ps += __shfl_xor_sync(0xffffffffu, ps, 2);
            ps += __shfl_xor_sync(0xffffffffu, ps, 1);
            lrow[r] = lrow[r] * corr + ps;
            f32x2_t cc = splat2(corr);
            scale2(o2[r][0], cc);
            scale2(o2[r][1], cc);
            // Stage P tile (float4, padded stride)
            *(float4*)(Ps + (tr * 4 + r) * PSTR + tc * 4) =
                make_float4(sc[r][0], sc[r][1], sc[r][2], sc[r][3]);
        }

        // Prefetch next tile's K/V (hidden under P-sync + PV loop)
        if (jt + 1 < TILES_PER_SPLIT) {
            ldg_kv(Kh + (size_t)(j0 + BJ) * D_, Vh + (size_t)(j0 + BJ) * D_, tid, kk, vv);
        }

        __syncthreads();  // P + V visible

        // O += P * V  (packed f32x2)
#pragma unroll 4
        for (int j = 0; j < BJ; j += 4) {
            float4 pr[4];
#pragma unroll
            for (int r = 0; r < 4; r++)
                pr[r] = *(const float4*)(Ps + (tr * 4 + r) * PSTR + j);
#pragma unroll
            for (int jj = 0; jj < 4; jj++) {
                float4 v = *(const float4*)(Vs + (j + jj) * D_ + tc * 4);
                f32x2_t v01 = pack2(v.x, v.y);
                f32x2_t v23 = pack2(v.z, v.w);
#pragma unroll
                for (int r = 0; r < 4; r++) {
                    float p = ((const float*)&pr[r])[jj];
                    f32x2_t pp = splat2(p);
                    fma2(o2[r][0], pp, v01);
                    fma2(o2[r][1], pp, v23);
                }
            }
        }
    }

    // Epilogue: store un-normalized partial O + (m, l)
    float* Op = g_Opart[split];
#pragma unroll
    for (int r = 0; r < 4; r++) {
        int ig = i0 + tr * 4 + r;
        float4 res;
        unpack2(res.x, res.y, o2[r][0]);
        unpack2(res.z, res.w, o2[r][1]);
        *(float4*)(Op + ((size_t)h * S_ + ig) * D_ + tc * 4) = res;
        if (tc == 0) g_ML[split][h * S_ + ig] = make_float2(mrow[r], lrow[r]);
    }
}

// ---------------------------------------------------------------------------
// Combine pass: merge NSPLIT partial softmax results.
// ---------------------------------------------------------------------------
__global__ __launch_bounds__(256) void combine_kernel(float* __restrict__ Og) {
    int idx = blockIdx.x * blockDim.x + threadIdx.x;  // over H_*S_*(D_/4)
    if (idx >= H_ * S_ * (D_ / 4)) return;
    int row = idx >> 4;          // D_/4 == 16
    int dcol = (idx & 15) * 4;

    float2 ml0 = g_ML[0][row];
    float2 ml1 = g_ML[1][row];
    float m = fmaxf(ml0.x, ml1.x);
    float a0 = __expf(ml0.x - m);
    float a1 = __expf(ml1.x - m);
    float inv = 1.0f / fmaf(ml0.y, a0, ml1.y * a1);

    float4 o0 = *(const float4*)&g_Opart[0][(size_t)row * D_ + dcol];
    float4 o1 = *(const float4*)&g_Opart[1][(size_t)row * D_ + dcol];
    float4 r;
    r.x = fmaf(o0.x, a0, o1.x * a1) * inv;
    r.y = fmaf(o0.y, a0, o1.y * a1) * inv;
    r.z = fmaf(o0.z, a0, o1.z * a1) * inv;
    r.w = fmaf(o0.w, a0, o1.w * a1) * inv;
    *(float4*)(Og + (size_t)row * D_ + dcol) = r;
}

// ---------------------------------------------------------------------------
// kernel_launch
// Input order: Q, K, V, distance_matrix, energy_matrix, mask,
//              mu_D, sigma_D, b_D, mu_E, sigma_E, b_E, W1, b1, W2, b2
// ---------------------------------------------------------------------------
extern "C" void kernel_launch(void* const* d_in, const int* in_sizes, int n_in,
                              void* d_out, int out_size) {
    const float* Q  = (const float*)d_in[0];
    const float* K  = (const float*)d_in[1];
    const float* V  = (const float*)d_in[2];
    const float* DM = (const float*)d_in[3];
    const float* EM = (const float*)d_in[4];
    const int*   MK = (const int*)d_in[5];
    const float* muD = (const float*)d_in[6];
    const float* sgD = (const float*)d_in[7];
    const float* bD  = (const float*)d_in[8];
    const float* muE = (const float*)d_in[9];
    const float* sgE = (const float*)d_in[10];
    const float* bE  = (const float*)d_in[11];
    const float* W1  = (const float*)d_in[12];
    const float* b1  = (const float*)d_in[13];
    const float* W2  = (const float*)d_in[14];
    const float* b2  = (const float*)d_in[15];
    float* Og = (float*)d_out;

    const int smem_bytes = 2 * LUTN * (int)sizeof(float2) +
                           (D_ * QSTR + D_ * QSTR + BJ * D_ + BI * PSTR) * (int)sizeof(float);

    cudaFuncSetAttribute(attn_partial_kernel, cudaFuncAttributeMaxDynamicSharedMemorySize, smem_bytes);

    int nev = 2 * (LUTN + 1);
    build_vals_kernel<<<(nev + 255) / 256, 256>>>(muD, sgD, bD, muE, sgE, bE, W1, b1, W2, b2);
    build_slopes_kernel<<<(LUTN + 255) / 256, 256>>>();

    dim3 grid(S_ / BI, H_, NSPLIT);
    attn_partial_kernel<<<grid, NT, smem_bytes>>>(Q, K, V, DM, EM, MK);

    int nc = H_ * S_ * (D_ / 4);
    combine_kernel<<<(nc + 255) / 256, 256>>>(Og);
}

// round 4
// speedup vs baseline: 1.5614x; 1.5614x over previous
#include <cuda_runtime.h>
#include <math.h>
#include <stdint.h>

// Problem constants (B=1)
#define H_   8
#define S_   1024
#define D_   64
#define KG_  10

// Tiling
#define BI   64
#define BJ   64
#define NT   256
#define NSPLIT 2
#define TILES_PER_SPLIT (S_ / BJ / NSPLIT)

// LUT
#define LUTN    2048
#define RANGE_D 10.0f
#define RANGE_E 5.0f

// smem strides (padded)
#define QSTR 68   // transposed Q/K tiles: [D][BI+4]; 68*4=272 bytes = 16B-aligned rows
#define PSTR 68   // P tile: [BI][BJ+4]

__device__ float2 g_lutD[LUTN];
__device__ float2 g_lutE[LUTN];
__device__ float  g_vals[2][LUTN + 1];
// split-KV scratch (static __device__: no allocation)
__device__ float  g_Opart[NSPLIT][H_ * S_ * D_];
__device__ float2 g_ML[NSPLIT][H_ * S_];

// ---------------------------------------------------------------------------
// Packed fp32x2 helpers (Blackwell FFMA2 — only reachable via PTX)
// ---------------------------------------------------------------------------
typedef unsigned long long f32x2_t;
__device__ __forceinline__ f32x2_t splat2(float x) {
    f32x2_t r; asm("mov.b64 %0, {%1, %1};" : "=l"(r) : "f"(x)); return r;
}
__device__ __forceinline__ void fma2(f32x2_t& d, f32x2_t a, f32x2_t b) {
    asm("fma.rn.f32x2 %0, %1, %2, %0;" : "+l"(d) : "l"(a), "l"(b));
}
__device__ __forceinline__ void scale2(f32x2_t& d, f32x2_t s) {
    asm("mul.rn.f32x2 %0, %0, %1;" : "+l"(d) : "l"(s));
}
__device__ __forceinline__ void unpack2(float& lo, float& hi, f32x2_t v) {
    asm("mov.b64 {%0, %1}, %2;" : "=f"(lo), "=f"(hi) : "l"(v));
}

// ---------------------------------------------------------------------------
// LUT construction: full RBF -> MLP(exact GELU) bias, one eval per thread.
// ---------------------------------------------------------------------------
__device__ __forceinline__ float gelu_exact(float x) {
    return 0.5f * x * (1.0f + erff(x * 0.70710678118654752f));
}

__device__ float bias_eval(float x,
                           const float* __restrict__ mu, const float* __restrict__ sg,
                           const float* __restrict__ bb,
                           const float* __restrict__ W1, const float* __restrict__ b1,
                           const float* __restrict__ W2, float b2v) {
    float psi[KG_];
#pragma unroll
    for (int k = 0; k < KG_; k++) {
        float s = sg[k];
        float z = (x + bb[k] - mu[k]) / s;
        psi[k] = expf(-0.5f * z * z) * (0.3989422804014327f / s);
    }
    float acc = b2v;
#pragma unroll
    for (int l = 0; l < KG_; l++) {
        float hv = b1[l];
#pragma unroll
        for (int k = 0; k < KG_; k++) hv = fmaf(W1[l * KG_ + k], psi[k], hv);
        acc = fmaf(W2[l], gelu_exact(hv), acc);
    }
    return acc;
}

__global__ void build_vals_kernel(const float* __restrict__ muD, const float* __restrict__ sgD,
                                  const float* __restrict__ bD,
                                  const float* __restrict__ muE, const float* __restrict__ sgE,
                                  const float* __restrict__ bE,
                                  const float* __restrict__ W1, const float* __restrict__ b1,
                                  const float* __restrict__ W2, const float* __restrict__ b2) {
    int idx = blockIdx.x * blockDim.x + threadIdx.x;
    if (idx >= 2 * (LUTN + 1)) return;
    int which = idx / (LUTN + 1);
    int i = idx % (LUTN + 1);
    float b2v = b2[0];
    if (which == 0) {
        g_vals[0][i] = bias_eval((float)i * (RANGE_D / (float)LUTN), muD, sgD, bD, W1, b1, W2, b2v);
    } else {
        g_vals[1][i] = bias_eval((float)i * (RANGE_E / (float)LUTN), muE, sgE, bE, W1, b1, W2, b2v);
    }
}

__global__ void build_slopes_kernel() {
    int i = blockIdx.x * blockDim.x + threadIdx.x;
    if (i >= LUTN) return;
    float d0 = g_vals[0][i];
    g_lutD[i] = make_float2(d0, g_vals[0][i + 1] - d0);
    float e0 = g_vals[1][i];
    g_lutE[i] = make_float2(e0, g_vals[1][i + 1] - e0);
}

// ---------------------------------------------------------------------------
// Fused flash attention with LUT biases. Split-KV partial kernel.
// grid = (S/BI, H, NSPLIT), block = 256 (16x16 thread grid, 4x4 micro-tile).
// ---------------------------------------------------------------------------
__device__ __forceinline__ float lut_interp(const float2* __restrict__ lut, float x, float scale) {
    float t = x * scale;
    int ix = (int)t;
    ix = max(0, min(ix, LUTN - 1));
    float f = t - (float)ix;
    float2 e = lut[ix];
    return fmaf(e.y, f, e.x);
}

__global__ __launch_bounds__(NT, 2) void attn_partial_kernel(
    const float* __restrict__ Qg, const float* __restrict__ Kg, const float* __restrict__ Vg,
    const float* __restrict__ DMg, const float* __restrict__ EMg, const int* __restrict__ Mg) {
    extern __shared__ unsigned char smraw[];
    float2* lutD = (float2*)smraw;
    float2* lutE = lutD + LUTN;
    float* Qs = (float*)(lutE + LUTN);   // [D][QSTR] transposed
    float* Ks = Qs + D_ * QSTR;          // [D][QSTR] transposed
    float* Vs = Ks + D_ * QSTR;          // [BJ][D]
    float* Ps = Vs + BJ * D_;            // [BI][PSTR]

    const int tid = threadIdx.x;
    const int h = blockIdx.y;
    const int i0 = blockIdx.x * BI;
    const int split = blockIdx.z;
    const int tr = tid >> 4;   // 0..15: query-row group
    const int tc = tid & 15;   // 0..15: col group

    const float lscaleD = (float)LUTN / RANGE_D;
    const float lscaleE = (float)LUTN / RANGE_E;

    // Stage LUTs into shared (coalesced)
    for (int t = tid; t < LUTN; t += NT) lutD[t] = g_lutD[t];
    for (int t = tid; t < LUTN; t += NT) lutE[t] = g_lutE[t];

    // Load Q tile transposed: Qs[d][i]
    const float* Qbase = Qg + ((size_t)h * S_ + i0) * D_;
#pragma unroll
    for (int k = 0; k < (BI * D_ / 4) / NT; k++) {
        int fi = tid + k * NT;          // 0..1023
        int row = fi >> 4;              // 16 float4 per row
        int dcol = (fi & 15) * 4;
        float4 q = *(const float4*)(Qbase + row * D_ + dcol);
        Qs[(dcol + 0) * QSTR + row] = q.x;
        Qs[(dcol + 1) * QSTR + row] = q.y;
        Qs[(dcol + 2) * QSTR + row] = q.z;
        Qs[(dcol + 3) * QSTR + row] = q.w;
    }

    f32x2_t o2[4][2];
    float mrow[4], lrow[4];
#pragma unroll
    for (int r = 0; r < 4; r++) {
        mrow[r] = -1e30f;
        lrow[r] = 0.f;
        o2[r][0] = 0ull;
        o2[r][1] = 0ull;
    }

    const float qk_scale = 0.0883883476483184f;  // 1/sqrt(2*D)

    for (int jt = 0; jt < TILES_PER_SPLIT; jt++) {
        const int j0 = (split * TILES_PER_SPLIT + jt) * BJ;
        __syncthreads();  // prev-iter P/K/V consumers done

        // Load K tile transposed: Ks[d][j]
        const float* Kbase = Kg + ((size_t)h * S_ + j0) * D_;
#pragma unroll
        for (int k = 0; k < 4; k++) {
            int fi = tid + k * NT;
            int row = fi >> 4;
            int dcol = (fi & 15) * 4;
            float4 v = *(const float4*)(Kbase + row * D_ + dcol);
            Ks[(dcol + 0) * QSTR + row] = v.x;
            Ks[(dcol + 1) * QSTR + row] = v.y;
            Ks[(dcol + 2) * QSTR + row] = v.z;
            Ks[(dcol + 3) * QSTR + row] = v.w;
        }
        // Load V tile straight: Vs[j][d]
        const float* Vbase = Vg + ((size_t)h * S_ + j0) * D_;
#pragma unroll
        for (int k = 0; k < 4; k++) {
            int fi = tid + k * NT;
            *(float4*)(Vs + fi * 4) = *(const float4*)(Vbase + fi * 4);
        }

        // Issue global loads for bias matrices + mask (latency hidden under QK)
        float4 dm[4], em[4];
        int4 mk[4];
#pragma unroll
        for (int r = 0; r < 4; r++) {
            int ig = i0 + tr * 4 + r;
            size_t base = ((size_t)h * S_ + ig) * S_ + j0 + tc * 4;
            dm[r] = *(const float4*)(DMg + base);
            em[r] = *(const float4*)(EMg + base);
            mk[r] = *(const int4*)(Mg + base);
        }

        __syncthreads();  // tiles visible

        // QK^T: 4x4 micro-tile per thread, packed f32x2 (FFMA2).
        // b loaded as ulonglong2 -> natural b64 register pairs (no pack MOVs).
        f32x2_t sc2[4][2];
#pragma unroll
        for (int r = 0; r < 4; r++) { sc2[r][0] = 0ull; sc2[r][1] = 0ull; }

#pragma unroll 8
        for (int k = 0; k < D_; k++) {
            float4 a = *(const float4*)(Qs + k * QSTR + tr * 4);
            ulonglong2 b = *(const ulonglong2*)(Ks + k * QSTR + tc * 4);
            float av[4] = {a.x, a.y, a.z, a.w};
#pragma unroll
            for (int r = 0; r < 4; r++) {
                f32x2_t aa = splat2(av[r]);
                fma2(sc2[r][0], aa, b.x);
                fma2(sc2[r][1], aa, b.y);
            }
        }

        // unpack, scale + LUT biases + mask
        float sc[4][4];
#pragma unroll
        for (int r = 0; r < 4; r++) {
            unpack2(sc[r][0], sc[r][1], sc2[r][0]);
            unpack2(sc[r][2], sc[r][3], sc2[r][1]);
            const float* dp = (const float*)&dm[r];
            const float* ep = (const float*)&em[r];
            const int* mp = (const int*)&mk[r];
#pragma unroll
            for (int c = 0; c < 4; c++) {
                float s = sc[r][c] * qk_scale
                        + lut_interp(lutD, dp[c], lscaleD)
                        + lut_interp(lutE, ep[c], lscaleE);
                sc[r][c] = (mp[c] == 0) ? -1e9f : s;
            }
        }

        // Online softmax over this tile (row reduce across 16 lanes)
#pragma unroll
        for (int r = 0; r < 4; r++) {
            float mx = fmaxf(fmaxf(sc[r][0], sc[r][1]), fmaxf(sc[r][2], sc[r][3]));
            mx = fmaxf(mx, __shfl_xor_sync(0xffffffffu, mx, 8));
            mx = fmaxf(mx, __shfl_xor_sync(0xffffffffu, mx, 4));
            mx = fmaxf(mx, __shfl_xor_sync(0xffffffffu, mx, 2));
            mx = fmaxf(mx, __shfl_xor_sync(0xffffffffu, mx, 1));
            float mnew = fmaxf(mrow[r], mx);
            float corr = __expf(mrow[r] - mnew);
            mrow[r] = mnew;
            float ps = 0.f;
#pragma unroll
            for (int c = 0; c < 4; c++) {
                float p = __expf(sc[r][c] - mnew);
                sc[r][c] = p;
                ps += p;
            }
            ps += __shfl_xor_sync(0xffffffffu, ps, 8);
            ps += __shfl_xor_sync(0xffffffffu, ps, 4);
            ps += __shfl_xor_sync(0xffffffffu, ps, 2);
            ps += __shfl_xor_sync(0xffffffffu, ps, 1);
            lrow[r] = lrow[r] * corr + ps;
            f32x2_t cc = splat2(corr);
            scale2(o2[r][0], cc);
            scale2(o2[r][1], cc);
            // Stage P tile (float4, padded stride)
            *(float4*)(Ps + (tr * 4 + r) * PSTR + tc * 4) =
                make_float4(sc[r][0], sc[r][1], sc[r][2], sc[r][3]);
        }

        __syncthreads();  // P + V visible

        // O += P * V  (packed f32x2; v as ulonglong2 -> no pack MOVs)
#pragma unroll 4
        for (int j = 0; j < BJ; j += 4) {
            float4 pr[4];
#pragma unroll
            for (int r = 0; r < 4; r++)
                pr[r] = *(const float4*)(Ps + (tr * 4 + r) * PSTR + j);
#pragma unroll
            for (int jj = 0; jj < 4; jj++) {
                ulonglong2 v = *(const ulonglong2*)(Vs + (j + jj) * D_ + tc * 4);
#pragma unroll
                for (int r = 0; r < 4; r++) {
                    f32x2_t pp = splat2(((const float*)&pr[r])[jj]);
                    fma2(o2[r][0], pp, v.x);
                    fma2(o2[r][1], pp, v.y);
                }
            }
        }
    }

    // Epilogue: store un-normalized partial O + (m, l)
    float* Op = g_Opart[split];
#pragma unroll
    for (int r = 0; r < 4; r++) {
        int ig = i0 + tr * 4 + r;
        float4 res;
        unpack2(res.x, res.y, o2[r][0]);
        unpack2(res.z, res.w, o2[r][1]);
        *(float4*)(Op + ((size_t)h * S_ + ig) * D_ + tc * 4) = res;
        if (tc == 0) g_ML[split][h * S_ + ig] = make_float2(mrow[r], lrow[r]);
    }
}

// ---------------------------------------------------------------------------
// Combine pass: merge NSPLIT partial softmax results. 2 rows per thread (MLP).
// ---------------------------------------------------------------------------
#define COMB_N (H_ * S_ * (D_ / 4))
__global__ __launch_bounds__(256) void combine_kernel(float* __restrict__ Og) {
    int idx0 = blockIdx.x * blockDim.x + threadIdx.x;
#pragma unroll
    for (int half = 0; half < 2; half++) {
        int idx = idx0 + half * (COMB_N / 2);
        int row = idx >> 4;          // D_/4 == 16
        int dcol = (idx & 15) * 4;

        float2 ml0 = g_ML[0][row];
        float2 ml1 = g_ML[1][row];
        float4 o0 = *(const float4*)&g_Opart[0][(size_t)row * D_ + dcol];
        float4 o1 = *(const float4*)&g_Opart[1][(size_t)row * D_ + dcol];

        float m = fmaxf(ml0.x, ml1.x);
        float a0 = __expf(ml0.x - m);
        float a1 = __expf(ml1.x - m);
        float inv = 1.0f / fmaf(ml0.y, a0, ml1.y * a1);

        float4 r;
        r.x = fmaf(o0.x, a0, o1.x * a1) * inv;
        r.y = fmaf(o0.y, a0, o1.y * a1) * inv;
        r.z = fmaf(o0.z, a0, o1.z * a1) * inv;
        r.w = fmaf(o0.w, a0, o1.w * a1) * inv;
        *(float4*)(Og + (size_t)row * D_ + dcol) = r;
    }
}

// ---------------------------------------------------------------------------
// kernel_launch
// Input order: Q, K, V, distance_matrix, energy_matrix, mask,
//              mu_D, sigma_D, b_D, mu_E, sigma_E, b_E, W1, b1, W2, b2
// ---------------------------------------------------------------------------
extern "C" void kernel_launch(void* const* d_in, const int* in_sizes, int n_in,
                              void* d_out, int out_size) {
    const float* Q  = (const float*)d_in[0];
    const float* K  = (const float*)d_in[1];
    const float* V  = (const float*)d_in[2];
    const float* DM = (const float*)d_in[3];
    const float* EM = (const float*)d_in[4];
    const int*   MK = (const int*)d_in[5];
    const float* muD = (const float*)d_in[6];
    const float* sgD = (const float*)d_in[7];
    const float* bD  = (const float*)d_in[8];
    const float* muE = (const float*)d_in[9];
    const float* sgE = (const float*)d_in[10];
    const float* bE  = (const float*)d_in[11];
    const float* W1  = (const float*)d_in[12];
    const float* b1  = (const float*)d_in[13];
    const float* W2  = (const float*)d_in[14];
    const float* b2  = (const float*)d_in[15];
    float* Og = (float*)d_out;

    const int smem_bytes = 2 * LUTN * (int)sizeof(float2) +
                           (D_ * QSTR + D_ * QSTR + BJ * D_ + BI * PSTR) * (int)sizeof(float);

    cudaFuncSetAttribute(attn_partial_kernel, cudaFuncAttributeMaxDynamicSharedMemorySize, smem_bytes);

    int nev = 2 * (LUTN + 1);
    build_vals_kernel<<<(nev + 255) / 256, 256>>>(muD, sgD, bD, muE, sgE, bE, W1, b1, W2, b2);
    build_slopes_kernel<<<(LUTN + 255) / 256, 256>>>();

    dim3 grid(S_ / BI, H_, NSPLIT);
    attn_partial_kernel<<<grid, NT, smem_bytes>>>(Q, K, V, DM, EM, MK);

    combine_kernel<<<(COMB_N / 2 + 255) / 256, 256>>>(Og);
}

// round 7
// speedup vs baseline: 1.7775x; 1.1384x over previous
#include <cuda_runtime.h>
#include <math.h>
#include <stdint.h>

// Problem constants (B=1)
#define H_   8
#define S_   1024
#define D_   64
#define KG_  10

// Tiling
#define BI   64
#define BJ   64
#define NT   256
#define NSPLIT 2
#define TILES_PER_SPLIT (S_ / BJ / NSPLIT)

// LUT
#define LUTN    2048
#define RANGE_D 10.0f
#define RANGE_E 5.0f

// smem strides (chosen for conflict-free mma fragment loads)
#define QSTR 68   // Q rows [i][d]
#define KSTR 68   // K rows [j][d]
#define VSTR 72   // V rows [j][d]
#define PSTR 68   // P rows [i][j]

__device__ float2 g_lutD[LUTN];
__device__ float2 g_lutE[LUTN];
__device__ float  g_vals[2][LUTN + 1];
// split-KV scratch (static __device__: no allocation)
__device__ float  g_Opart[NSPLIT][H_ * S_ * D_];
__device__ float2 g_ML[NSPLIT][H_ * S_];

// ---------------------------------------------------------------------------
// tf32 helpers (3xTF32 precision scheme)
// ---------------------------------------------------------------------------
__device__ __forceinline__ uint32_t f2tf(float x) {
    uint32_t r; asm("cvt.rna.tf32.f32 %0, %1;" : "=r"(r) : "f"(x)); return r;
}
__device__ __forceinline__ void split_tf32(float x, uint32_t& hi, uint32_t& lo) {
    hi = f2tf(x);
    float res = x - __uint_as_float(hi);
    lo = f2tf(res);
}
// D(16x8,f32) += A(16x8,tf32) * B(8x8,tf32)
__device__ __forceinline__ void mma_tf32(float* c, const uint32_t* a, const uint32_t* b) {
    asm volatile(
        "mma.sync.aligned.m16n8k8.row.col.f32.tf32.tf32.f32 "
        "{%0,%1,%2,%3}, {%4,%5,%6,%7}, {%8,%9}, {%0,%1,%2,%3};"
        : "+f"(c[0]), "+f"(c[1]), "+f"(c[2]), "+f"(c[3])
        : "r"(a[0]), "r"(a[1]), "r"(a[2]), "r"(a[3]), "r"(b[0]), "r"(b[1]));
}

// ---------------------------------------------------------------------------
// LUT construction: full RBF -> MLP(exact GELU) bias, one eval per thread.
// ---------------------------------------------------------------------------
__device__ __forceinline__ float gelu_exact(float x) {
    return 0.5f * x * (1.0f + erff(x * 0.70710678118654752f));
}

__device__ float bias_eval(float x,
                           const float* __restrict__ mu, const float* __restrict__ sg,
                           const float* __restrict__ bb,
                           const float* __restrict__ W1, const float* __restrict__ b1,
                           const float* __restrict__ W2, float b2v) {
    float psi[KG_];
#pragma unroll
    for (int k = 0; k < KG_; k++) {
        float s = sg[k];
        float z = (x + bb[k] - mu[k]) / s;
        psi[k] = expf(-0.5f * z * z) * (0.3989422804014327f / s);
    }
    float acc = b2v;
#pragma unroll
    for (int l = 0; l < KG_; l++) {
        float hv = b1[l];
#pragma unroll
        for (int k = 0; k < KG_; k++) hv = fmaf(W1[l * KG_ + k], psi[k], hv);
        acc = fmaf(W2[l], gelu_exact(hv), acc);
    }
    return acc;
}

__global__ void build_vals_kernel(const float* __restrict__ muD, const float* __restrict__ sgD,
                                  const float* __restrict__ bD,
                                  const float* __restrict__ muE, const float* __restrict__ sgE,
                                  const float* __restrict__ bE,
                                  const float* __restrict__ W1, const float* __restrict__ b1,
                                  const float* __restrict__ W2, const float* __restrict__ b2) {
    int idx = blockIdx.x * blockDim.x + threadIdx.x;
    if (idx >= 2 * (LUTN + 1)) return;
    int which = idx / (LUTN + 1);
    int i = idx % (LUTN + 1);
    float b2v = b2[0];
    if (which == 0) {
        g_vals[0][i] = bias_eval((float)i * (RANGE_D / (float)LUTN), muD, sgD, bD, W1, b1, W2, b2v);
    } else {
        g_vals[1][i] = bias_eval((float)i * (RANGE_E / (float)LUTN), muE, sgE, bE, W1, b1, W2, b2v);
    }
}

__global__ void build_slopes_kernel() {
    int i = blockIdx.x * blockDim.x + threadIdx.x;
    if (i >= LUTN) return;
    float d0 = g_vals[0][i];
    g_lutD[i] = make_float2(d0, g_vals[0][i + 1] - d0);
    float e0 = g_vals[1][i];
    g_lutE[i] = make_float2(e0, g_vals[1][i + 1] - e0);
}

// ---------------------------------------------------------------------------
// Fused flash attention, tf32 mma version. Split-KV partial kernel.
// grid = (S/BI, H, NSPLIT), block = 256 = 8 warps.
// Warp w covers rows [ (w/2)*16, +16 ) and cols [ (w%2)*32, +32 ) of the 64x64 tile.
// Softmax row-statistics are reduced ACROSS the warp pair (same wr) via smem.
// ---------------------------------------------------------------------------
__device__ __forceinline__ float lut_interp(const float2* __restrict__ lut, float x, float scale) {
    float t = x * scale;
    int ix = (int)t;
    ix = max(0, min(ix, LUTN - 1));
    float f = t - (float)ix;
    float2 e = lut[ix];
    return fmaf(e.y, f, e.x);
}

__global__ __launch_bounds__(NT, 2) void attn_partial_kernel(
    const float* __restrict__ Qg, const float* __restrict__ Kg, const float* __restrict__ Vg,
    const float* __restrict__ DMg, const float* __restrict__ EMg, const int* __restrict__ Mg) {
    extern __shared__ unsigned char smraw[];
    float2* lutD = (float2*)smraw;
    float2* lutE = lutD + LUTN;
    float* Qs = (float*)(lutE + LUTN);   // [64][QSTR]
    float* Ks = Qs + BI * QSTR;          // [64][KSTR]
    float* Vs = Ks + BJ * KSTR;          // [64][VSTR]
    float* Ps = Vs + BJ * VSTR;          // [64][PSTR]
    float* redm = Ps + BI * PSTR;        // [2][64] partial row max
    float* reds = redm + 2 * BI;         // [2][64] partial row sum

    const int tid = threadIdx.x;
    const int warp = tid >> 5;
    const int lane = tid & 31;
    const int qr = lane >> 2;
    const int qc = lane & 3;
    const int wr = warp >> 1;        // row-block 0..3 (16 rows each)
    const int wc = warp & 1;         // col-half 0..1 (32 cols each)

    const int h = blockIdx.y;
    const int i0 = blockIdx.x * BI;
    const int split = blockIdx.z;

    const float lscaleD = (float)LUTN / RANGE_D;
    const float lscaleE = (float)LUTN / RANGE_E;
    const float qk_scale = 0.0883883476483184f;  // 1/sqrt(2*D)

    // Stage LUTs into shared (coalesced)
    for (int t = tid; t < LUTN; t += NT) lutD[t] = g_lutD[t];
    for (int t = tid; t < LUTN; t += NT) lutE[t] = g_lutE[t];

    // Load Q tile [i][d] (straight copy, stride QSTR)
    const float* Qbase = Qg + ((size_t)h * S_ + i0) * D_;
#pragma unroll
    for (int k = 0; k < 4; k++) {
        int fi = tid + k * NT;
        int row = fi >> 4;
        int col = (fi & 15) * 4;
        float4 q = *(const float4*)(Qbase + row * D_ + col);
        *(float4*)(Qs + row * QSTR + col) = q;
    }

    // Per-thread state: O frags for 4 col-blocks; m/l for 2 rows
    float o[4][4];
#pragma unroll
    for (int cb = 0; cb < 4; cb++)
#pragma unroll
        for (int e = 0; e < 4; e++) o[cb][e] = 0.f;
    float m2[2] = {-1e30f, -1e30f};
    float l2[2] = {0.f, 0.f};

    const int row0l = wr * 16 + qr;      // local row (0..63)
    const int row1l = row0l + 8;

    for (int jt = 0; jt < TILES_PER_SPLIT; jt++) {
        const int j0 = (split * TILES_PER_SPLIT + jt) * BJ;

        // Early-issue bias loads: float2 per (row, col-block)
        float2 dm2[2][4], em2[2][4];
        {
            size_t rbase0 = ((size_t)h * S_ + (i0 + row0l)) * S_ + j0;
            size_t rbase1 = ((size_t)h * S_ + (i0 + row1l)) * S_ + j0;
#pragma unroll
            for (int cb = 0; cb < 4; cb++) {
                int colg = (wc * 4 + cb) * 8 + qc * 2;
                dm2[0][cb] = *(const float2*)(DMg + rbase0 + colg);
                dm2[1][cb] = *(const float2*)(DMg + rbase1 + colg);
                em2[0][cb] = *(const float2*)(EMg + rbase0 + colg);
                em2[1][cb] = *(const float2*)(EMg + rbase1 + colg);
            }
        }

        __syncthreads();  // all warps done with prev K/V/P

        // Load K,V tiles [j][d] straight
        const float* Kbase = Kg + ((size_t)h * S_ + j0) * D_;
        const float* Vbase = Vg + ((size_t)h * S_ + j0) * D_;
#pragma unroll
        for (int k = 0; k < 4; k++) {
            int fi = tid + k * NT;
            int row = fi >> 4;
            int col = (fi & 15) * 4;
            *(float4*)(Ks + row * KSTR + col) = *(const float4*)(Kbase + row * D_ + col);
            *(float4*)(Vs + row * VSTR + col) = *(const float4*)(Vbase + row * D_ + col);
        }

        __syncthreads();  // tiles visible

        // ---- QK^T via 3xTF32 mma ----
        float sc[4][4];
#pragma unroll
        for (int cb = 0; cb < 4; cb++)
#pragma unroll
            for (int e = 0; e < 4; e++) sc[cb][e] = 0.f;

#pragma unroll
        for (int kk = 0; kk < 8; kk++) {
            float ax0 = Qs[row0l * QSTR + kk * 8 + qc];
            float ax1 = Qs[row1l * QSTR + kk * 8 + qc];
            float ax2 = Qs[row0l * QSTR + kk * 8 + qc + 4];
            float ax3 = Qs[row1l * QSTR + kk * 8 + qc + 4];
            uint32_t ah[4], al[4];
            split_tf32(ax0, ah[0], al[0]);
            split_tf32(ax1, ah[1], al[1]);
            split_tf32(ax2, ah[2], al[2]);
            split_tf32(ax3, ah[3], al[3]);
#pragma unroll
            for (int cb = 0; cb < 4; cb++) {
                int n = (wc * 4 + cb) * 8 + qr;      // local j
                float bx0 = Ks[n * KSTR + kk * 8 + qc];
                float bx1 = Ks[n * KSTR + kk * 8 + qc + 4];
                uint32_t bh[2], bl[2];
                split_tf32(bx0, bh[0], bl[0]);
                split_tf32(bx1, bh[1], bl[1]);
                mma_tf32(sc[cb], ah, bh);
                mma_tf32(sc[cb], ah, bl);
                mma_tf32(sc[cb], al, bh);
            }
        }

        // Mask loads
        int2 mk2[2][4];
        {
            size_t rbase0 = ((size_t)h * S_ + (i0 + row0l)) * S_ + j0;
            size_t rbase1 = ((size_t)h * S_ + (i0 + row1l)) * S_ + j0;
#pragma unroll
            for (int cb = 0; cb < 4; cb++) {
                int colg = (wc * 4 + cb) * 8 + qc * 2;
                mk2[0][cb] = *(const int2*)(Mg + rbase0 + colg);
                mk2[1][cb] = *(const int2*)(Mg + rbase1 + colg);
            }
        }

        // ---- scale + LUT biases + mask ----
#pragma unroll
        for (int cb = 0; cb < 4; cb++) {
            float s0 = sc[cb][0] * qk_scale + lut_interp(lutD, dm2[0][cb].x, lscaleD)
                     + lut_interp(lutE, em2[0][cb].x, lscaleE);
            float s1 = sc[cb][1] * qk_scale + lut_interp(lutD, dm2[0][cb].y, lscaleD)
                     + lut_interp(lutE, em2[0][cb].y, lscaleE);
            float s2 = sc[cb][2] * qk_scale + lut_interp(lutD, dm2[1][cb].x, lscaleD)
                     + lut_interp(lutE, em2[1][cb].x, lscaleE);
            float s3 = sc[cb][3] * qk_scale + lut_interp(lutD, dm2[1][cb].y, lscaleD)
                     + lut_interp(lutE, em2[1][cb].y, lscaleE);
            sc[cb][0] = (mk2[0][cb].x == 0) ? -1e9f : s0;
            sc[cb][1] = (mk2[0][cb].y == 0) ? -1e9f : s1;
            sc[cb][2] = (mk2[1][cb].x == 0) ? -1e9f : s2;
            sc[cb][3] = (mk2[1][cb].y == 0) ? -1e9f : s3;
        }

        // ---- online softmax, reduced across the warp pair via smem ----
        // Step 1: per-warp partial row max (over this warp's 32 cols)
        float mxp[2];
#pragma unroll
        for (int r = 0; r < 2; r++) {
            int e0 = r * 2, e1 = e0 + 1;
            float v = fmaxf(fmaxf(sc[0][e0], sc[0][e1]), fmaxf(sc[1][e0], sc[1][e1]));
            v = fmaxf(v, fmaxf(fmaxf(sc[2][e0], sc[2][e1]), fmaxf(sc[3][e0], sc[3][e1])));
            v = fmaxf(v, __shfl_xor_sync(0xffffffffu, v, 1));
            v = fmaxf(v, __shfl_xor_sync(0xffffffffu, v, 2));
            mxp[r] = v;
            if (qc == 0) redm[wc * BI + ((r == 0) ? row0l : row1l)] = v;
        }

        __syncthreads();  // partial maxes visible

        // Step 2: full-row max -> exp, partial sums, P staging, O rescale
        float corr2[2];
#pragma unroll
        for (int r = 0; r < 2; r++) {
            int e0 = r * 2, e1 = e0 + 1;
            int rowl = (r == 0) ? row0l : row1l;
            float mfull = fmaxf(mxp[r], redm[(1 - wc) * BI + rowl]);
            float mnew = fmaxf(m2[r], mfull);
            corr2[r] = __expf(m2[r] - mnew);
            m2[r] = mnew;
            float ps = 0.f;
#pragma unroll
            for (int cb = 0; cb < 4; cb++) {
                float p0 = __expf(sc[cb][e0] - mnew);
                float p1 = __expf(sc[cb][e1] - mnew);
                sc[cb][e0] = p0;
                sc[cb][e1] = p1;
                ps += p0 + p1;
            }
            ps += __shfl_xor_sync(0xffffffffu, ps, 1);
            ps += __shfl_xor_sync(0xffffffffu, ps, 2);
            if (qc == 0) reds[wc * BI + rowl] = ps;
#pragma unroll
            for (int cb = 0; cb < 4; cb++) {
                o[cb][e0] *= corr2[r];
                o[cb][e1] *= corr2[r];
                *(float2*)(Ps + rowl * PSTR + (wc * 4 + cb) * 8 + qc * 2) =
                    make_float2(sc[cb][e0], sc[cb][e1]);
            }
        }

        __syncthreads();  // partial sums + full P tile visible

        // Step 3: fold full-row sum into l
#pragma unroll
        for (int r = 0; r < 2; r++) {
            int rowl = (r == 0) ? row0l : row1l;
            float total = reds[rowl] + reds[BI + rowl];
            l2[r] = l2[r] * corr2[r] + total;
        }

        // ---- O += P * V via 3xTF32 mma ----
#pragma unroll
        for (int kk = 0; kk < 8; kk++) {
            float px0 = Ps[row0l * PSTR + kk * 8 + qc];
            float px1 = Ps[row1l * PSTR + kk * 8 + qc];
            float px2 = Ps[row0l * PSTR + kk * 8 + qc + 4];
            float px3 = Ps[row1l * PSTR + kk * 8 + qc + 4];
            uint32_t ah[4], al[4];
            split_tf32(px0, ah[0], al[0]);
            split_tf32(px1, ah[1], al[1]);
            split_tf32(px2, ah[2], al[2]);
            split_tf32(px3, ah[3], al[3]);
#pragma unroll
            for (int cb = 0; cb < 4; cb++) {
                int n = wc * 32 + cb * 8 + qr;       // output d column
                float bx0 = Vs[(kk * 8 + qc) * VSTR + n];
                float bx1 = Vs[(kk * 8 + qc + 4) * VSTR + n];
                uint32_t bh[2], bl[2];
                split_tf32(bx0, bh[0], bl[0]);
                split_tf32(bx1, bh[1], bl[1]);
                mma_tf32(o[cb], ah, bh);
                mma_tf32(o[cb], ah, bl);
                mma_tf32(o[cb], al, bh);
            }
        }
    }

    // ---- Epilogue: store un-normalized partial O + (m, l) ----
    float* Op = g_Opart[split];
    int ig0 = i0 + row0l;
    int ig1 = i0 + row1l;
#pragma unroll
    for (int cb = 0; cb < 4; cb++) {
        int dcol = (wc * 4 + cb) * 8 + qc * 2;
        *(float2*)(Op + ((size_t)h * S_ + ig0) * D_ + dcol) = make_float2(o[cb][0], o[cb][1]);
        *(float2*)(Op + ((size_t)h * S_ + ig1) * D_ + dcol) = make_float2(o[cb][2], o[cb][3]);
    }
    if (qc == 0 && wc == 0) {
        g_ML[split][h * S_ + ig0] = make_float2(m2[0], l2[0]);
        g_ML[split][h * S_ + ig1] = make_float2(m2[1], l2[1]);
    }
}

// ---------------------------------------------------------------------------
// Combine pass: merge NSPLIT partial softmax results. 2 rows per thread (MLP).
// ---------------------------------------------------------------------------
#define COMB_N (H_ * S_ * (D_ / 4))
__global__ __launch_bounds__(256) void combine_kernel(float* __restrict__ Og) {
    int idx0 = blockIdx.x * blockDim.x + threadIdx.x;
#pragma unroll
    for (int half = 0; half < 2; half++) {
        int idx = idx0 + half * (COMB_N / 2);
        int row = idx >> 4;          // D_/4 == 16
        int dcol = (idx & 15) * 4;

        float2 ml0 = g_ML[0][row];
        float2 ml1 = g_ML[1][row];
        float4 o0 = *(const float4*)&g_Opart[0][(size_t)row * D_ + dcol];
        float4 o1 = *(const float4*)&g_Opart[1][(size_t)row * D_ + dcol];

        float m = fmaxf(ml0.x, ml1.x);
        float a0 = __expf(ml0.x - m);
        float a1 = __expf(ml1.x - m);
        float inv = 1.0f / fmaf(ml0.y, a0, ml1.y * a1);

        float4 r;
        r.x = fmaf(o0.x, a0, o1.x * a1) * inv;
        r.y = fmaf(o0.y, a0, o1.y * a1) * inv;
        r.z = fmaf(o0.z, a0, o1.z * a1) * inv;
        r.w = fmaf(o0.w, a0, o1.w * a1) * inv;
        *(float4*)(Og + (size_t)row * D_ + dcol) = r;
    }
}

// ---------------------------------------------------------------------------
// kernel_launch
// Input order: Q, K, V, distance_matrix, energy_matrix, mask,
//              mu_D, sigma_D, b_D, mu_E, sigma_E, b_E, W1, b1, W2, b2
// ---------------------------------------------------------------------------
extern "C" void kernel_launch(void* const* d_in, const int* in_sizes, int n_in,
                              void* d_out, int out_size) {
    const float* Q  = (const float*)d_in[0];
    const float* K  = (const float*)d_in[1];
    const float* V  = (const float*)d_in[2];
    const float* DM = (const float*)d_in[3];
    const float* EM = (const float*)d_in[4];
    const int*   MK = (const int*)d_in[5];
    const float* muD = (const float*)d_in[6];
    const float* sgD = (const float*)d_in[7];
    const float* bD  = (const float*)d_in[8];
    const float* muE = (const float*)d_in[9];
    const float* sgE = (const float*)d_in[10];
    const float* bE  = (const float*)d_in[11];
    const float* W1  = (const float*)d_in[12];
    const float* b1  = (const float*)d_in[13];
    const float* W2  = (const float*)d_in[14];
    const float* b2  = (const float*)d_in[15];
    float* Og = (float*)d_out;

    const int smem_bytes = 2 * LUTN * (int)sizeof(float2) +
                           (BI * QSTR + BJ * KSTR + BJ * VSTR + BI * PSTR + 4 * BI) * (int)sizeof(float);

    cudaFuncSetAttribute(attn_partial_kernel, cudaFuncAttributeMaxDynamicSharedMemorySize, smem_bytes);

    int nev = 2 * (LUTN + 1);
    build_vals_kernel<<<(nev + 255) / 256, 256>>>(muD, sgD, bD, muE, sgE, bE, W1, b1, W2, b2);
    build_slopes_kernel<<<(LUTN + 255) / 256, 256>>>();

    dim3 grid(S_ / BI, H_, NSPLIT);
    attn_partial_kernel<<<grid, NT, smem_bytes>>>(Q, K, V, DM, EM, MK);

    combine_kernel<<<(COMB_N / 2 + 255) / 256, 256>>>(Og);
}

// round 9
// speedup vs baseline: 1.8979x; 1.0677x over previous
#include <cuda_runtime.h>
#include <cuda_bf16.h>
#include <math.h>
#include <stdint.h>

// Problem constants (B=1)
#define H_   8
#define S_   1024
#define D_   64
#define KG_  10

// Tiling
#define BI   64
#define BJ   64
#define NT   256
#define NSPLIT 2
#define TILES_PER_SPLIT (S_ / BJ / NSPLIT)

// LUT
#define LUTN    2048
#define RANGE_D 10.0f
#define RANGE_E 5.0f

// bf16 tile stride: 72 elements = 144 bytes = 36 words; 36 mod 32 == 4
// -> fragment-load bank = (4*qr + qc) + const : conflict-free.
#define QS 72

__device__ float2 g_lutD[LUTN];
__device__ float2 g_lutE[LUTN];
__device__ float  g_vals[2][LUTN + 1];
// split-KV scratch (static __device__: no allocation)
__device__ float  g_Opart[NSPLIT][H_ * S_ * D_];
__device__ float2 g_ML[NSPLIT][H_ * S_];

// ---------------------------------------------------------------------------
// bf16 split helpers (3-term split-bf16 scheme)
// ---------------------------------------------------------------------------
__device__ __forceinline__ void split_bf(float x, float& hi, float& lo) {
    __nv_bfloat16 h = __float2bfloat16_rn(x);
    hi = __bfloat162float(h);
    lo = x - hi;
}
__device__ __forceinline__ uint32_t pack_bf2(float a, float b) {
    __nv_bfloat162 t = __floats2bfloat162_rn(a, b);   // .x=a (low), .y=b (high)
    return *reinterpret_cast<uint32_t*>(&t);
}
// D(16x8,f32) += A(16x16,bf16) * B(16x8,bf16)
__device__ __forceinline__ void mma_bf16(float* c, const uint32_t* a, const uint32_t* b) {
    asm volatile(
        "mma.sync.aligned.m16n8k16.row.col.f32.bf16.bf16.f32 "
        "{%0,%1,%2,%3}, {%4,%5,%6,%7}, {%8,%9}, {%0,%1,%2,%3};"
        : "+f"(c[0]), "+f"(c[1]), "+f"(c[2]), "+f"(c[3])
        : "r"(a[0]), "r"(a[1]), "r"(a[2]), "r"(a[3]), "r"(b[0]), "r"(b[1]));
}

// ---------------------------------------------------------------------------
// LUT construction: full RBF -> MLP(exact GELU) bias, one eval per thread.
// ---------------------------------------------------------------------------
__device__ __forceinline__ float gelu_exact(float x) {
    return 0.5f * x * (1.0f + erff(x * 0.70710678118654752f));
}

__device__ float bias_eval(float x,
                           const float* __restrict__ mu, const float* __restrict__ sg,
                           const float* __restrict__ bb,
                           const float* __restrict__ W1, const float* __restrict__ b1,
                           const float* __restrict__ W2, float b2v) {
    float psi[KG_];
#pragma unroll
    for (int k = 0; k < KG_; k++) {
        float s = sg[k];
        float z = (x + bb[k] - mu[k]) / s;
        psi[k] = expf(-0.5f * z * z) * (0.3989422804014327f / s);
    }
    float acc = b2v;
#pragma unroll
    for (int l = 0; l < KG_; l++) {
        float hv = b1[l];
#pragma unroll
        for (int k = 0; k < KG_; k++) hv = fmaf(W1[l * KG_ + k], psi[k], hv);
        acc = fmaf(W2[l], gelu_exact(hv), acc);
    }
    return acc;
}

__global__ void build_vals_kernel(const float* __restrict__ muD, const float* __restrict__ sgD,
                                  const float* __restrict__ bD,
                                  const float* __restrict__ muE, const float* __restrict__ sgE,
                                  const float* __restrict__ bE,
                                  const float* __restrict__ W1, const float* __restrict__ b1,
                                  const float* __restrict__ W2, const float* __restrict__ b2) {
    int idx = blockIdx.x * blockDim.x + threadIdx.x;
    if (idx >= 2 * (LUTN + 1)) return;
    int which = idx / (LUTN + 1);
    int i = idx % (LUTN + 1);
    float b2v = b2[0];
    if (which == 0) {
        g_vals[0][i] = bias_eval((float)i * (RANGE_D / (float)LUTN), muD, sgD, bD, W1, b1, W2, b2v);
    } else {
        g_vals[1][i] = bias_eval((float)i * (RANGE_E / (float)LUTN), muE, sgE, bE, W1, b1, W2, b2v);
    }
}

__global__ void build_slopes_kernel() {
    int i = blockIdx.x * blockDim.x + threadIdx.x;
    if (i >= LUTN) return;
    float d0 = g_vals[0][i];
    g_lutD[i] = make_float2(d0, g_vals[0][i + 1] - d0);
    float e0 = g_vals[1][i];
    g_lutE[i] = make_float2(e0, g_vals[1][i + 1] - e0);
}

// ---------------------------------------------------------------------------
// Fused flash attention, split-bf16 mma version. Split-KV partial kernel.
// grid = (S/BI, H, NSPLIT), block = 256 = 8 warps.
// Warp w: rows [(w/2)*16,+16), cols [(w%2)*32,+32) of the 64x64 tile.
// Softmax row stats reduced across the warp pair via smem (validated R7).
// m16n8k16 fragments (qr=lane/4, qc=lane%4), k-base = kk*16:
//   A: a0(r=qr, k=2qc) a1(r=qr+8, k=2qc) a2(r=qr, k=2qc+8) a3(r=qr+8, k=2qc+8)
//      each a-word = bf16 pair (k, k+1): contiguous row-major load.
//   B: b0(k=2qc, n=qr) b1(k=2qc+8, n=qr): contiguous pair along k in row n
//      of a [n][k]-major tile (K rows; V stored transposed).
//   C: c0(r=qr,c=2qc) c1(+1) c2(r=qr+8) c3(r=qr+8,+1)
// ---------------------------------------------------------------------------
__device__ __forceinline__ float lut_interp(const float2* __restrict__ lut, float x, float scale) {
    float t = x * scale;
    int ix = (int)t;
    ix = max(0, min(ix, LUTN - 1));
    float f = t - (float)ix;
    float2 e = lut[ix];
    return fmaf(e.y, f, e.x);
}

__global__ __launch_bounds__(NT, 2) void attn_partial_kernel(
    const float* __restrict__ Qg, const float* __restrict__ Kg, const float* __restrict__ Vg,
    const float* __restrict__ DMg, const float* __restrict__ EMg, const int* __restrict__ Mg) {
    extern __shared__ unsigned char smraw[];
    float2* lutD = (float2*)smraw;
    float2* lutE = lutD + LUTN;
    __nv_bfloat16* Qhi = (__nv_bfloat16*)(lutE + LUTN);   // [64][QS]
    __nv_bfloat16* Qlo = Qhi + BI * QS;
    __nv_bfloat16* Khi = Qlo + BI * QS;                   // [j][d]
    __nv_bfloat16* Klo = Khi + BJ * QS;
    __nv_bfloat16* Vthi = Klo + BJ * QS;                  // transposed [d][j]
    __nv_bfloat16* Vtlo = Vthi + D_ * QS;
    __nv_bfloat16* Phi = Vtlo + D_ * QS;                  // [i][j]
    __nv_bfloat16* Plo = Phi + BI * QS;
    float* redm = (float*)(Plo + BI * QS);                // [2][64]
    float* reds = redm + 2 * BI;                          // [2][64]

    const int tid = threadIdx.x;
    const int warp = tid >> 5;
    const int lane = tid & 31;
    const int qr = lane >> 2;
    const int qc = lane & 3;
    const int wr = warp >> 1;
    const int wc = warp & 1;

    const int h = blockIdx.y;
    const int i0 = blockIdx.x * BI;
    const int split = blockIdx.z;

    const float lscaleD = (float)LUTN / RANGE_D;
    const float lscaleE = (float)LUTN / RANGE_E;
    const float qk_scale = 0.0883883476483184f;  // 1/sqrt(2*D)

    // Stage LUTs into shared
    for (int t = tid; t < LUTN; t += NT) lutD[t] = g_lutD[t];
    for (int t = tid; t < LUTN; t += NT) lutE[t] = g_lutE[t];

    // Stage Q split once: [i][d] bf16 hi/lo
    const float* Qbase = Qg + ((size_t)h * S_ + i0) * D_;
#pragma unroll
    for (int k = 0; k < 4; k++) {
        int fi = tid + k * NT;
        int row = fi >> 4;
        int col = (fi & 15) * 4;
        float4 q = *(const float4*)(Qbase + row * D_ + col);
        float h0, l0, h1, l1, h2, l2, h3, l3;
        split_bf(q.x, h0, l0); split_bf(q.y, h1, l1);
        split_bf(q.z, h2, l2); split_bf(q.w, h3, l3);
        *(uint32_t*)(Qhi + row * QS + col)     = pack_bf2(h0, h1);
        *(uint32_t*)(Qhi + row * QS + col + 2) = pack_bf2(h2, h3);
        *(uint32_t*)(Qlo + row * QS + col)     = pack_bf2(l0, l1);
        *(uint32_t*)(Qlo + row * QS + col + 2) = pack_bf2(l2, l3);
    }

    float o[4][4];
#pragma unroll
    for (int cb = 0; cb < 4; cb++)
#pragma unroll
        for (int e = 0; e < 4; e++) o[cb][e] = 0.f;
    float m2[2] = {-1e30f, -1e30f};
    float l2a[2] = {0.f, 0.f};

    const int row0l = wr * 16 + qr;
    const int row1l = row0l + 8;

    for (int jt = 0; jt < TILES_PER_SPLIT; jt++) {
        const int j0 = (split * TILES_PER_SPLIT + jt) * BJ;

        // Early-issue bias loads
        float2 dm2[2][4], em2[2][4];
        {
            size_t rbase0 = ((size_t)h * S_ + (i0 + row0l)) * S_ + j0;
            size_t rbase1 = ((size_t)h * S_ + (i0 + row1l)) * S_ + j0;
#pragma unroll
            for (int cb = 0; cb < 4; cb++) {
                int colg = (wc * 4 + cb) * 8 + qc * 2;
                dm2[0][cb] = *(const float2*)(DMg + rbase0 + colg);
                dm2[1][cb] = *(const float2*)(DMg + rbase1 + colg);
                em2[0][cb] = *(const float2*)(EMg + rbase0 + colg);
                em2[1][cb] = *(const float2*)(EMg + rbase1 + colg);
            }
        }

        __syncthreads();  // prev-tile consumers done

        // Stage K (split, [j][d]) and V (split, transposed [d][j])
        const float* Kbase = Kg + ((size_t)h * S_ + j0) * D_;
        const float* Vbase = Vg + ((size_t)h * S_ + j0) * D_;
#pragma unroll
        for (int k = 0; k < 4; k++) {
            int fi = tid + k * NT;
            int row = fi >> 4;          // j
            int col = (fi & 15) * 4;    // d
            float4 kv = *(const float4*)(Kbase + row * D_ + col);
            float4 vv = *(const float4*)(Vbase + row * D_ + col);
            float h0, l0, h1, l1, h2, l2, h3, l3;
            split_bf(kv.x, h0, l0); split_bf(kv.y, h1, l1);
            split_bf(kv.z, h2, l2); split_bf(kv.w, h3, l3);
            *(uint32_t*)(Khi + row * QS + col)     = pack_bf2(h0, h1);
            *(uint32_t*)(Khi + row * QS + col + 2) = pack_bf2(h2, h3);
            *(uint32_t*)(Klo + row * QS + col)     = pack_bf2(l0, l1);
            *(uint32_t*)(Klo + row * QS + col + 2) = pack_bf2(l2, l3);
            split_bf(vv.x, h0, l0); split_bf(vv.y, h1, l1);
            split_bf(vv.z, h2, l2); split_bf(vv.w, h3, l3);
            Vthi[(col + 0) * QS + row] = __float2bfloat16_rn(h0);
            Vthi[(col + 1) * QS + row] = __float2bfloat16_rn(h1);
            Vthi[(col + 2) * QS + row] = __float2bfloat16_rn(h2);
            Vthi[(col + 3) * QS + row] = __float2bfloat16_rn(h3);
            Vtlo[(col + 0) * QS + row] = __float2bfloat16_rn(l0);
            Vtlo[(col + 1) * QS + row] = __float2bfloat16_rn(l1);
            Vtlo[(col + 2) * QS + row] = __float2bfloat16_rn(l2);
            Vtlo[(col + 3) * QS + row] = __float2bfloat16_rn(l3);
        }

        __syncthreads();  // tiles visible

        // ---- QK^T: pure LDS + bf16 mma (3-term) ----
        float sc[4][4];
#pragma unroll
        for (int cb = 0; cb < 4; cb++)
#pragma unroll
            for (int e = 0; e < 4; e++) sc[cb][e] = 0.f;

#pragma unroll
        for (int kk = 0; kk < 4; kk++) {
            int k0 = kk * 16 + qc * 2;
            uint32_t ah[4], al[4];
            ah[0] = *(const uint32_t*)(Qhi + row0l * QS + k0);
            ah[1] = *(const uint32_t*)(Qhi + row1l * QS + k0);
            ah[2] = *(const uint32_t*)(Qhi + row0l * QS + k0 + 8);
            ah[3] = *(const uint32_t*)(Qhi + row1l * QS + k0 + 8);
            al[0] = *(const uint32_t*)(Qlo + row0l * QS + k0);
            al[1] = *(const uint32_t*)(Qlo + row1l * QS + k0);
            al[2] = *(const uint32_t*)(Qlo + row0l * QS + k0 + 8);
            al[3] = *(const uint32_t*)(Qlo + row1l * QS + k0 + 8);
#pragma unroll
            for (int cb = 0; cb < 4; cb++) {
                int n = (wc * 4 + cb) * 8 + qr;
                uint32_t bh[2], bl[2];
                bh[0] = *(const uint32_t*)(Khi + n * QS + k0);
                bh[1] = *(const uint32_t*)(Khi + n * QS + k0 + 8);
                bl[0] = *(const uint32_t*)(Klo + n * QS + k0);
                bl[1] = *(const uint32_t*)(Klo + n * QS + k0 + 8);
                mma_bf16(sc[cb], ah, bh);
                mma_bf16(sc[cb], ah, bl);
                mma_bf16(sc[cb], al, bh);
            }
        }

        // Mask loads
        int2 mk2[2][4];
        {
            size_t rbase0 = ((size_t)h * S_ + (i0 + row0l)) * S_ + j0;
            size_t rbase1 = ((size_t)h * S_ + (i0 + row1l)) * S_ + j0;
#pragma unroll
            for (int cb = 0; cb < 4; cb++) {
                int colg = (wc * 4 + cb) * 8 + qc * 2;
                mk2[0][cb] = *(const int2*)(Mg + rbase0 + colg);
                mk2[1][cb] = *(const int2*)(Mg + rbase1 + colg);
            }
        }

        // ---- scale + LUT biases + mask ----
#pragma unroll
        for (int cb = 0; cb < 4; cb++) {
            float s0 = sc[cb][0] * qk_scale + lut_interp(lutD, dm2[0][cb].x, lscaleD)
                     + lut_interp(lutE, em2[0][cb].x, lscaleE);
            float s1 = sc[cb][1] * qk_scale + lut_interp(lutD, dm2[0][cb].y, lscaleD)
                     + lut_interp(lutE, em2[0][cb].y, lscaleE);
            float s2 = sc[cb][2] * qk_scale + lut_interp(lutD, dm2[1][cb].x, lscaleD)
                     + lut_interp(lutE, em2[1][cb].x, lscaleE);
            float s3 = sc[cb][3] * qk_scale + lut_interp(lutD, dm2[1][cb].y, lscaleD)
                     + lut_interp(lutE, em2[1][cb].y, lscaleE);
            sc[cb][0] = (mk2[0][cb].x == 0) ? -1e9f : s0;
            sc[cb][1] = (mk2[0][cb].y == 0) ? -1e9f : s1;
            sc[cb][2] = (mk2[1][cb].x == 0) ? -1e9f : s2;
            sc[cb][3] = (mk2[1][cb].y == 0) ? -1e9f : s3;
        }

        // ---- online softmax across the warp pair (smem reduce) ----
        float mxp[2];
#pragma unroll
        for (int r = 0; r < 2; r++) {
            int e0 = r * 2, e1 = e0 + 1;
            float v = fmaxf(fmaxf(sc[0][e0], sc[0][e1]), fmaxf(sc[1][e0], sc[1][e1]));
            v = fmaxf(v, fmaxf(fmaxf(sc[2][e0], sc[2][e1]), fmaxf(sc[3][e0], sc[3][e1])));
            v = fmaxf(v, __shfl_xor_sync(0xffffffffu, v, 1));
            v = fmaxf(v, __shfl_xor_sync(0xffffffffu, v, 2));
            mxp[r] = v;
            if (qc == 0) redm[wc * BI + ((r == 0) ? row0l : row1l)] = v;
        }

        __syncthreads();

        float corr2[2];
#pragma unroll
        for (int r = 0; r < 2; r++) {
            int e0 = r * 2, e1 = e0 + 1;
            int rowl = (r == 0) ? row0l : row1l;
            float mfull = fmaxf(mxp[r], redm[(1 - wc) * BI + rowl]);
            float mnew = fmaxf(m2[r], mfull);
            corr2[r] = __expf(m2[r] - mnew);
            m2[r] = mnew;
            float ps = 0.f;
#pragma unroll
            for (int cb = 0; cb < 4; cb++) {
                float p0 = __expf(sc[cb][e0] - mnew);
                float p1 = __expf(sc[cb][e1] - mnew);
                sc[cb][e0] = p0;
                sc[cb][e1] = p1;
                ps += p0 + p1;
            }
            ps += __shfl_xor_sync(0xffffffffu, ps, 1);
            ps += __shfl_xor_sync(0xffffffffu, ps, 2);
            if (qc == 0) reds[wc * BI + rowl] = ps;
#pragma unroll
            for (int cb = 0; cb < 4; cb++) {
                o[cb][e0] *= corr2[r];
                o[cb][e1] *= corr2[r];
                // split P and stage hi/lo
                float h0, l0, h1, l1;
                split_bf(sc[cb][e0], h0, l0);
                split_bf(sc[cb][e1], h1, l1);
                int col = (wc * 4 + cb) * 8 + qc * 2;
                *(uint32_t*)(Phi + rowl * QS + col) = pack_bf2(h0, h1);
                *(uint32_t*)(Plo + rowl * QS + col) = pack_bf2(l0, l1);
            }
        }

        __syncthreads();  // sums + full P tile visible

#pragma unroll
        for (int r = 0; r < 2; r++) {
            int rowl = (r == 0) ? row0l : row1l;
            float total = reds[rowl] + reds[BI + rowl];
            l2a[r] = l2a[r] * corr2[r] + total;
        }

        // ---- O += P * V: pure LDS + bf16 mma (3-term) ----
#pragma unroll
        for (int kk = 0; kk < 4; kk++) {
            int k0 = kk * 16 + qc * 2;
            uint32_t ah[4], al[4];
            ah[0] = *(const uint32_t*)(Phi + row0l * QS + k0);
            ah[1] = *(const uint32_t*)(Phi + row1l * QS + k0);
            ah[2] = *(const uint32_t*)(Phi + row0l * QS + k0 + 8);
            ah[3] = *(const uint32_t*)(Phi + row1l * QS + k0 + 8);
            al[0] = *(const uint32_t*)(Plo + row0l * QS + k0);
            al[1] = *(const uint32_t*)(Plo + row1l * QS + k0);
            al[2] = *(const uint32_t*)(Plo + row0l * QS + k0 + 8);
            al[3] = *(const uint32_t*)(Plo + row1l * QS + k0 + 8);
#pragma unroll
            for (int cb = 0; cb < 4; cb++) {
                int n = wc * 32 + cb * 8 + qr;       // output d column
                uint32_t bh[2], bl[2];
                bh[0] = *(const uint32_t*)(Vthi + n * QS + k0);
                bh[1] = *(const uint32_t*)(Vthi + n * QS + k0 + 8);
                bl[0] = *(const uint32_t*)(Vtlo + n * QS + k0);
                bl[1] = *(const uint32_t*)(Vtlo + n * QS + k0 + 8);
                mma_bf16(o[cb], ah, bh);
                mma_bf16(o[cb], ah, bl);
                mma_bf16(o[cb], al, bh);
            }
        }
    }

    // ---- Epilogue: store un-normalized partial O + (m, l) ----
    float* Op = g_Opart[split];
    int ig0 = i0 + row0l;
    int ig1 = i0 + row1l;
#pragma unroll
    for (int cb = 0; cb < 4; cb++) {
        int dcol = (wc * 4 + cb) * 8 + qc * 2;
        *(float2*)(Op + ((size_t)h * S_ + ig0) * D_ + dcol) = make_float2(o[cb][0], o[cb][1]);
        *(float2*)(Op + ((size_t)h * S_ + ig1) * D_ + dcol) = make_float2(o[cb][2], o[cb][3]);
    }
    if (qc == 0 && wc == 0) {
        g_ML[split][h * S_ + ig0] = make_float2(m2[0], l2a[0]);
        g_ML[split][h * S_ + ig1] = make_float2(m2[1], l2a[1]);
    }
}

// ---------------------------------------------------------------------------
// Combine pass: merge NSPLIT partial softmax results. 2 rows per thread (MLP).
// ---------------------------------------------------------------------------
#define COMB_N (H_ * S_ * (D_ / 4))
__global__ __launch_bounds__(256) void combine_kernel(float* __restrict__ Og) {
    int idx0 = blockIdx.x * blockDim.x + threadIdx.x;
#pragma unroll
    for (int half = 0; half < 2; half++) {
        int idx = idx0 + half * (COMB_N / 2);
        int row = idx >> 4;          // D_/4 == 16
        int dcol = (idx & 15) * 4;

        float2 ml0 = g_ML[0][row];
        float2 ml1 = g_ML[1][row];
        float4 o0 = *(const float4*)&g_Opart[0][(size_t)row * D_ + dcol];
        float4 o1 = *(const float4*)&g_Opart[1][(size_t)row * D_ + dcol];

        float m = fmaxf(ml0.x, ml1.x);
        float a0 = __expf(ml0.x - m);
        float a1 = __expf(ml1.x - m);
        float inv = 1.0f / fmaf(ml0.y, a0, ml1.y * a1);

        float4 r;
        r.x = fmaf(o0.x, a0, o1.x * a1) * inv;
        r.y = fmaf(o0.y, a0, o1.y * a1) * inv;
        r.z = fmaf(o0.z, a0, o1.z * a1) * inv;
        r.w = fmaf(o0.w, a0, o1.w * a1) * inv;
        *(float4*)(Og + (size_t)row * D_ + dcol) = r;
    }
}

// ---------------------------------------------------------------------------
// kernel_launch
// Input order: Q, K, V, distance_matrix, energy_matrix, mask,
//              mu_D, sigma_D, b_D, mu_E, sigma_E, b_E, W1, b1, W2, b2
// ---------------------------------------------------------------------------
extern "C" void kernel_launch(void* const* d_in, const int* in_sizes, int n_in,
                              void* d_out, int out_size) {
    const float* Q  = (const float*)d_in[0];
    const float* K  = (const float*)d_in[1];
    const float* V  = (const float*)d_in[2];
    const float* DM = (const float*)d_in[3];
    const float* EM = (const float*)d_in[4];
    const int*   MK = (const int*)d_in[5];
    const float* muD = (const float*)d_in[6];
    const float* sgD = (const float*)d_in[7];
    const float* bD  = (const float*)d_in[8];
    const float* muE = (const float*)d_in[9];
    const float* sgE = (const float*)d_in[10];
    const float* bE  = (const float*)d_in[11];
    const float* W1  = (const float*)d_in[12];
    const float* b1  = (const float*)d_in[13];
    const float* W2  = (const float*)d_in[14];
    const float* b2  = (const float*)d_in[15];
    float* Og = (float*)d_out;

    const int smem_bytes = 2 * LUTN * (int)sizeof(float2)
                         + 8 * BI * QS * (int)sizeof(__nv_bfloat16)
                         + 4 * BI * (int)sizeof(float);

    cudaFuncSetAttribute(attn_partial_kernel, cudaFuncAttributeMaxDynamicSharedMemorySize, smem_bytes);

    int nev = 2 * (LUTN + 1);
    build_vals_kernel<<<(nev + 255) / 256, 256>>>(muD, sgD, bD, muE, sgE, bE, W1, b1, W2, b2);
    build_slopes_kernel<<<(LUTN + 255) / 256, 256>>>();

    dim3 grid(S_ / BI, H_, NSPLIT);
    attn_partial_kernel<<<grid, NT, smem_bytes>>>(Q, K, V, DM, EM, MK);

    combine_kernel<<<(COMB_N / 2 + 255) / 256, 256>>>(Og);
}

// round 10
// speedup vs baseline: 2.2489x; 1.1849x over previous
#include <cuda_runtime.h>
#include <cuda_bf16.h>
#include <math.h>
#include <stdint.h>

// Problem constants (B=1)
#define H_   8
#define S_   1024
#define D_   64
#define KG_  10

// Tiling
#define BI   64
#define BJ   64
#define NT   256
#define NSPLIT 2
#define TILES_PER_SPLIT (S_ / BJ / NSPLIT)

// LUT
#define LUTN    2048
#define RANGE_D 10.0f
#define RANGE_E 5.0f

// bf16 tile stride: 72 elements = 144 bytes = 36 words; 36 mod 32 == 4
// -> every 8-lane ldmatrix phase hits banks 4l..4l+3 : conflict-free.
#define QS 72

__device__ float2 g_lutD[LUTN];
__device__ float2 g_lutE[LUTN];
__device__ float  g_vals[2][LUTN + 1];
// split-KV scratch (static __device__: no allocation)
__device__ float  g_Opart[NSPLIT][H_ * S_ * D_];
__device__ float2 g_ML[NSPLIT][H_ * S_];

// ---------------------------------------------------------------------------
// bf16 split helpers (3-term split-bf16 scheme)
// ---------------------------------------------------------------------------
__device__ __forceinline__ void split_bf(float x, float& hi, float& lo) {
    __nv_bfloat16 h = __float2bfloat16_rn(x);
    hi = __bfloat162float(h);
    lo = x - hi;
}
__device__ __forceinline__ uint32_t pack_bf2(float a, float b) {
    __nv_bfloat162 t = __floats2bfloat162_rn(a, b);   // .x=a (low), .y=b (high)
    return *reinterpret_cast<uint32_t*>(&t);
}
// D(16x8,f32) += A(16x16,bf16) * B(16x8,bf16)
__device__ __forceinline__ void mma_bf16(float* c, const uint32_t* a, const uint32_t* b) {
    asm volatile(
        "mma.sync.aligned.m16n8k16.row.col.f32.bf16.bf16.f32 "
        "{%0,%1,%2,%3}, {%4,%5,%6,%7}, {%8,%9}, {%0,%1,%2,%3};"
        : "+f"(c[0]), "+f"(c[1]), "+f"(c[2]), "+f"(c[3])
        : "r"(a[0]), "r"(a[1]), "r"(a[2]), "r"(a[3]), "r"(b[0]), "r"(b[1]));
}
__device__ __forceinline__ void ldsm_x4(uint32_t addr, uint32_t* r) {
    asm volatile("ldmatrix.sync.aligned.m8n8.x4.shared.b16 {%0,%1,%2,%3}, [%4];"
        : "=r"(r[0]), "=r"(r[1]), "=r"(r[2]), "=r"(r[3]) : "r"(addr));
}
__device__ __forceinline__ void ldsm_x4_trans(uint32_t addr, uint32_t* r) {
    asm volatile("ldmatrix.sync.aligned.m8n8.x4.trans.shared.b16 {%0,%1,%2,%3}, [%4];"
        : "=r"(r[0]), "=r"(r[1]), "=r"(r[2]), "=r"(r[3]) : "r"(addr));
}

// ---------------------------------------------------------------------------
// LUT construction: full RBF -> MLP(exact GELU) bias, one eval per thread.
// ---------------------------------------------------------------------------
__device__ __forceinline__ float gelu_exact(float x) {
    return 0.5f * x * (1.0f + erff(x * 0.70710678118654752f));
}

__device__ float bias_eval(float x,
                           const float* __restrict__ mu, const float* __restrict__ sg,
                           const float* __restrict__ bb,
                           const float* __restrict__ W1, const float* __restrict__ b1,
                           const float* __restrict__ W2, float b2v) {
    float psi[KG_];
#pragma unroll
    for (int k = 0; k < KG_; k++) {
        float s = sg[k];
        float z = (x + bb[k] - mu[k]) / s;
        psi[k] = expf(-0.5f * z * z) * (0.3989422804014327f / s);
    }
    float acc = b2v;
#pragma unroll
    for (int l = 0; l < KG_; l++) {
        float hv = b1[l];
#pragma unroll
        for (int k = 0; k < KG_; k++) hv = fmaf(W1[l * KG_ + k], psi[k], hv);
        acc = fmaf(W2[l], gelu_exact(hv), acc);
    }
    return acc;
}

__global__ void build_vals_kernel(const float* __restrict__ muD, const float* __restrict__ sgD,
                                  const float* __restrict__ bD,
                                  const float* __restrict__ muE, const float* __restrict__ sgE,
                                  const float* __restrict__ bE,
                                  const float* __restrict__ W1, const float* __restrict__ b1,
                                  const float* __restrict__ W2, const float* __restrict__ b2) {
    int idx = blockIdx.x * blockDim.x + threadIdx.x;
    if (idx >= 2 * (LUTN + 1)) return;
    int which = idx / (LUTN + 1);
    int i = idx % (LUTN + 1);
    float b2v = b2[0];
    if (which == 0) {
        g_vals[0][i] = bias_eval((float)i * (RANGE_D / (float)LUTN), muD, sgD, bD, W1, b1, W2, b2v);
    } else {
        g_vals[1][i] = bias_eval((float)i * (RANGE_E / (float)LUTN), muE, sgE, bE, W1, b1, W2, b2v);
    }
}

__global__ void build_slopes_kernel() {
    int i = blockIdx.x * blockDim.x + threadIdx.x;
    if (i >= LUTN) return;
    float d0 = g_vals[0][i];
    g_lutD[i] = make_float2(d0, g_vals[0][i + 1] - d0);
    float e0 = g_vals[1][i];
    g_lutE[i] = make_float2(e0, g_vals[1][i + 1] - e0);
}

// ---------------------------------------------------------------------------
// Fused flash attention, split-bf16 mma + ldmatrix. Split-KV partial kernel.
// grid = (S/BI, H, NSPLIT), block = 256 = 8 warps.
// Warp w: rows [(w/2)*16,+16), cols [(w%2)*32,+32) of the 64x64 tile.
// Softmax row stats reduced across the warp pair via smem (validated R7).
// ---------------------------------------------------------------------------
__device__ __forceinline__ float lut_interp(const float2* __restrict__ lut, float x, float scale) {
    float t = x * scale;
    int ix = (int)t;
    ix = max(0, min(ix, LUTN - 1));
    float f = t - (float)ix;
    float2 e = lut[ix];
    return fmaf(e.y, f, e.x);
}

__global__ __launch_bounds__(NT, 2) void attn_partial_kernel(
    const float* __restrict__ Qg, const float* __restrict__ Kg, const float* __restrict__ Vg,
    const float* __restrict__ DMg, const float* __restrict__ EMg, const int* __restrict__ Mg) {
    extern __shared__ unsigned char smraw[];
    float2* lutD = (float2*)smraw;
    float2* lutE = lutD + LUTN;
    __nv_bfloat16* Qhi = (__nv_bfloat16*)(lutE + LUTN);   // [i][QS], pre-scaled by qk_scale
    __nv_bfloat16* Qlo = Qhi + BI * QS;
    __nv_bfloat16* Khi = Qlo + BI * QS;                   // [j][d]
    __nv_bfloat16* Klo = Khi + BJ * QS;
    __nv_bfloat16* Vhi = Klo + BJ * QS;                   // [j][d] natural (ldsm.trans)
    __nv_bfloat16* Vlo = Vhi + BJ * QS;
    __nv_bfloat16* Phi = Vlo + BJ * QS;                   // [i][j]
    __nv_bfloat16* Plo = Phi + BI * QS;
    float* redm = (float*)(Plo + BI * QS);                // [2][64]
    float* reds = redm + 2 * BI;                          // [2][64]

    const int tid = threadIdx.x;
    const int lane = tid & 31;
    const int warp = tid >> 5;
    const int qr = lane >> 2;
    const int qc = lane & 3;
    const int wr = warp >> 1;
    const int wc = warp & 1;

    const int h = blockIdx.y;
    const int i0 = blockIdx.x * BI;
    const int split = blockIdx.z;

    const float lscaleD = (float)LUTN / RANGE_D;
    const float lscaleE = (float)LUTN / RANGE_E;
    const float qk_scale = 0.0883883476483184f;  // 1/sqrt(2*D)

    // smem byte addresses for ldmatrix
    const uint32_t qhi_s = (uint32_t)__cvta_generic_to_shared(Qhi);
    const uint32_t qlo_s = (uint32_t)__cvta_generic_to_shared(Qlo);
    const uint32_t khi_s = (uint32_t)__cvta_generic_to_shared(Khi);
    const uint32_t klo_s = (uint32_t)__cvta_generic_to_shared(Klo);
    const uint32_t vhi_s = (uint32_t)__cvta_generic_to_shared(Vhi);
    const uint32_t vlo_s = (uint32_t)__cvta_generic_to_shared(Vlo);
    const uint32_t phi_s = (uint32_t)__cvta_generic_to_shared(Phi);
    const uint32_t plo_s = (uint32_t)__cvta_generic_to_shared(Plo);

    // Per-lane ldmatrix address components (bytes):
    // A-pattern (Q/P, row-major [row][k]): row = wr*16 + (lane&15), kblk = lane>>4
    const uint32_t aoff = (uint32_t)(((wr * 16 + (lane & 15)) * QS) * 2 + ((lane >> 4) << 4));
    // B-pattern (K, [n][k]): groups: g0->hi k0, g1->hi k0+8, g2->lo k0, g3->lo k0+8
    const uint32_t bk_base = ((lane >> 4) ? klo_s : khi_s)
                           + (uint32_t)(((lane & 7) * QS) * 2 + (((lane >> 3) & 1) << 4));
    // V-trans pattern ([k][n]): lanes 0-15 -> Vhi rows k0+(lane&15); 16-31 -> Vlo
    const uint32_t bv_base = ((lane >> 4) ? vlo_s : vhi_s)
                           + (uint32_t)(((lane & 15) * QS) * 2);

    // Stage LUTs into shared
    for (int t = tid; t < LUTN; t += NT) lutD[t] = g_lutD[t];
    for (int t = tid; t < LUTN; t += NT) lutE[t] = g_lutE[t];

    // Stage Q split once (pre-scaled by qk_scale): [i][d] bf16 hi/lo
    const float* Qbase = Qg + ((size_t)h * S_ + i0) * D_;
#pragma unroll
    for (int k = 0; k < 4; k++) {
        int fi = tid + k * NT;
        int row = fi >> 4;
        int col = (fi & 15) * 4;
        float4 q = *(const float4*)(Qbase + row * D_ + col);
        q.x *= qk_scale; q.y *= qk_scale; q.z *= qk_scale; q.w *= qk_scale;
        float h0, l0, h1, l1, h2, l2, h3, l3;
        split_bf(q.x, h0, l0); split_bf(q.y, h1, l1);
        split_bf(q.z, h2, l2); split_bf(q.w, h3, l3);
        *(uint32_t*)(Qhi + row * QS + col)     = pack_bf2(h0, h1);
        *(uint32_t*)(Qhi + row * QS + col + 2) = pack_bf2(h2, h3);
        *(uint32_t*)(Qlo + row * QS + col)     = pack_bf2(l0, l1);
        *(uint32_t*)(Qlo + row * QS + col + 2) = pack_bf2(l2, l3);
    }

    float o[4][4];
#pragma unroll
    for (int cb = 0; cb < 4; cb++)
#pragma unroll
        for (int e = 0; e < 4; e++) o[cb][e] = 0.f;
    float m2[2] = {-1e30f, -1e30f};
    float l2a[2] = {0.f, 0.f};

    const int row0l = wr * 16 + qr;
    const int row1l = row0l + 8;

    for (int jt = 0; jt < TILES_PER_SPLIT; jt++) {
        const int j0 = (split * TILES_PER_SPLIT + jt) * BJ;

        // Early-issue bias + mask loads
        float2 dm2[2][4], em2[2][4];
        int2 mk2[2][4];
        {
            size_t rbase0 = ((size_t)h * S_ + (i0 + row0l)) * S_ + j0;
            size_t rbase1 = ((size_t)h * S_ + (i0 + row1l)) * S_ + j0;
#pragma unroll
            for (int cb = 0; cb < 4; cb++) {
                int colg = (wc * 4 + cb) * 8 + qc * 2;
                dm2[0][cb] = *(const float2*)(DMg + rbase0 + colg);
                dm2[1][cb] = *(const float2*)(DMg + rbase1 + colg);
                em2[0][cb] = *(const float2*)(EMg + rbase0 + colg);
                em2[1][cb] = *(const float2*)(EMg + rbase1 + colg);
                mk2[0][cb] = *(const int2*)(Mg + rbase0 + colg);
                mk2[1][cb] = *(const int2*)(Mg + rbase1 + colg);
            }
        }

        __syncthreads();  // prev-tile consumers done

        // Stage K and V (both split, natural [j][d], vectorized stores)
        const float* Kbase = Kg + ((size_t)h * S_ + j0) * D_;
        const float* Vbase = Vg + ((size_t)h * S_ + j0) * D_;
#pragma unroll
        for (int k = 0; k < 4; k++) {
            int fi = tid + k * NT;
            int row = fi >> 4;          // j
            int col = (fi & 15) * 4;    // d
            float4 kv = *(const float4*)(Kbase + row * D_ + col);
            float4 vv = *(const float4*)(Vbase + row * D_ + col);
            float h0, l0, h1, l1, h2, l2, h3, l3;
            split_bf(kv.x, h0, l0); split_bf(kv.y, h1, l1);
            split_bf(kv.z, h2, l2); split_bf(kv.w, h3, l3);
            *(uint32_t*)(Khi + row * QS + col)     = pack_bf2(h0, h1);
            *(uint32_t*)(Khi + row * QS + col + 2) = pack_bf2(h2, h3);
            *(uint32_t*)(Klo + row * QS + col)     = pack_bf2(l0, l1);
            *(uint32_t*)(Klo + row * QS + col + 2) = pack_bf2(l2, l3);
            split_bf(vv.x, h0, l0); split_bf(vv.y, h1, l1);
            split_bf(vv.z, h2, l2); split_bf(vv.w, h3, l3);
            *(uint32_t*)(Vhi + row * QS + col)     = pack_bf2(h0, h1);
            *(uint32_t*)(Vhi + row * QS + col + 2) = pack_bf2(h2, h3);
            *(uint32_t*)(Vlo + row * QS + col)     = pack_bf2(l0, l1);
            *(uint32_t*)(Vlo + row * QS + col + 2) = pack_bf2(l2, l3);
        }

        __syncthreads();  // tiles visible

        // ---- QK^T: ldmatrix + bf16 mma (3-term) ----
        float sc[4][4];
#pragma unroll
        for (int cb = 0; cb < 4; cb++)
#pragma unroll
            for (int e = 0; e < 4; e++) sc[cb][e] = 0.f;

#pragma unroll
        for (int kk = 0; kk < 4; kk++) {
            uint32_t ah[4], al[4];
            ldsm_x4(qhi_s + aoff + kk * 32, ah);
            ldsm_x4(qlo_s + aoff + kk * 32, al);
#pragma unroll
            for (int cb = 0; cb < 4; cb++) {
                // {bh0, bh1, bl0, bl1} in one x4 (hi/lo mixed across lane groups)
                uint32_t b[4];
                ldsm_x4(bk_base + (uint32_t)((wc * 4 + cb) * 8 * QS * 2) + kk * 32, b);
                mma_bf16(sc[cb], ah, b);       // hi*hi
                mma_bf16(sc[cb], ah, b + 2);   // hi*lo
                mma_bf16(sc[cb], al, b);       // lo*hi
            }
        }

        // ---- LUT biases + mask (Q pre-scaled, so no qk_scale here) ----
#pragma unroll
        for (int cb = 0; cb < 4; cb++) {
            float s0 = sc[cb][0] + lut_interp(lutD, dm2[0][cb].x, lscaleD)
                     + lut_interp(lutE, em2[0][cb].x, lscaleE);
            float s1 = sc[cb][1] + lut_interp(lutD, dm2[0][cb].y, lscaleD)
                     + lut_interp(lutE, em2[0][cb].y, lscaleE);
            float s2 = sc[cb][2] + lut_interp(lutD, dm2[1][cb].x, lscaleD)
                     + lut_interp(lutE, em2[1][cb].x, lscaleE);
            float s3 = sc[cb][3] + lut_interp(lutD, dm2[1][cb].y, lscaleD)
                     + lut_interp(lutE, em2[1][cb].y, lscaleE);
            sc[cb][0] = (mk2[0][cb].x == 0) ? -1e9f : s0;
            sc[cb][1] = (mk2[0][cb].y == 0) ? -1e9f : s1;
            sc[cb][2] = (mk2[1][cb].x == 0) ? -1e9f : s2;
            sc[cb][3] = (mk2[1][cb].y == 0) ? -1e9f : s3;
        }

        // ---- online softmax across the warp pair (smem reduce) ----
        float mxp[2];
#pragma unroll
        for (int r = 0; r < 2; r++) {
            int e0 = r * 2, e1 = e0 + 1;
            float v = fmaxf(fmaxf(sc[0][e0], sc[0][e1]), fmaxf(sc[1][e0], sc[1][e1]));
            v = fmaxf(v, fmaxf(fmaxf(sc[2][e0], sc[2][e1]), fmaxf(sc[3][e0], sc[3][e1])));
            v = fmaxf(v, __shfl_xor_sync(0xffffffffu, v, 1));
            v = fmaxf(v, __shfl_xor_sync(0xffffffffu, v, 2));
            mxp[r] = v;
            if (qc == 0) redm[wc * BI + ((r == 0) ? row0l : row1l)] = v;
        }

        __syncthreads();

        float corr2[2];
#pragma unroll
        for (int r = 0; r < 2; r++) {
            int e0 = r * 2, e1 = e0 + 1;
            int rowl = (r == 0) ? row0l : row1l;
            float mfull = fmaxf(mxp[r], redm[(1 - wc) * BI + rowl]);
            float mnew = fmaxf(m2[r], mfull);
            corr2[r] = __expf(m2[r] - mnew);
            m2[r] = mnew;
            float ps = 0.f;
#pragma unroll
            for (int cb = 0; cb < 4; cb++) {
                float p0 = __expf(sc[cb][e0] - mnew);
                float p1 = __expf(sc[cb][e1] - mnew);
                sc[cb][e0] = p0;
                sc[cb][e1] = p1;
                ps += p0 + p1;
            }
            ps += __shfl_xor_sync(0xffffffffu, ps, 1);
            ps += __shfl_xor_sync(0xffffffffu, ps, 2);
            if (qc == 0) reds[wc * BI + rowl] = ps;
#pragma unroll
            for (int cb = 0; cb < 4; cb++) {
                o[cb][e0] *= corr2[r];
                o[cb][e1] *= corr2[r];
                float h0, l0, h1, l1;
                split_bf(sc[cb][e0], h0, l0);
                split_bf(sc[cb][e1], h1, l1);
                int col = (wc * 4 + cb) * 8 + qc * 2;
                *(uint32_t*)(Phi + rowl * QS + col) = pack_bf2(h0, h1);
                *(uint32_t*)(Plo + rowl * QS + col) = pack_bf2(l0, l1);
            }
        }

        __syncthreads();  // sums + full P tile visible

#pragma unroll
        for (int r = 0; r < 2; r++) {
            int rowl = (r == 0) ? row0l : row1l;
            float total = reds[rowl] + reds[BI + rowl];
            l2a[r] = l2a[r] * corr2[r] + total;
        }

        // ---- O += P * V: ldmatrix(+trans for V) + bf16 mma (3-term) ----
#pragma unroll
        for (int kk = 0; kk < 4; kk++) {
            uint32_t ah[4], al[4];
            ldsm_x4(phi_s + aoff + kk * 32, ah);
            ldsm_x4(plo_s + aoff + kk * 32, al);
#pragma unroll
            for (int cb = 0; cb < 4; cb++) {
                uint32_t b[4];
                // V natural [j][d]; trans gives (k=j, n=d) frags.
                ldsm_x4_trans(bv_base + (uint32_t)(kk * 16 * QS * 2)
                              + (uint32_t)((wc * 32 + cb * 8) * 2), b);
                mma_bf16(o[cb], ah, b);
                mma_bf16(o[cb], ah, b + 2);
                mma_bf16(o[cb], al, b);
            }
        }
    }

    // ---- Epilogue: store un-normalized partial O + (m, l) ----
    float* Op = g_Opart[split];
    int ig0 = i0 + row0l;
    int ig1 = i0 + row1l;
#pragma unroll
    for (int cb = 0; cb < 4; cb++) {
        int dcol = (wc * 4 + cb) * 8 + qc * 2;
        *(float2*)(Op + ((size_t)h * S_ + ig0) * D_ + dcol) = make_float2(o[cb][0], o[cb][1]);
        *(float2*)(Op + ((size_t)h * S_ + ig1) * D_ + dcol) = make_float2(o[cb][2], o[cb][3]);
    }
    if (qc == 0 && wc == 0) {
        g_ML[split][h * S_ + ig0] = make_float2(m2[0], l2a[0]);
        g_ML[split][h * S_ + ig1] = make_float2(m2[1], l2a[1]);
    }
}

// ---------------------------------------------------------------------------
// Combine pass: merge NSPLIT partial softmax results. 2 rows per thread (MLP).
// ---------------------------------------------------------------------------
#define COMB_N (H_ * S_ * (D_ / 4))
__global__ __launch_bounds__(256) void combine_kernel(float* __restrict__ Og) {
    int idx0 = blockIdx.x * blockDim.x + threadIdx.x;
#pragma unroll
    for (int half = 0; half < 2; half++) {
        int idx = idx0 + half * (COMB_N / 2);
        int row = idx >> 4;          // D_/4 == 16
        int dcol = (idx & 15) * 4;

        float2 ml0 = g_ML[0][row];
        float2 ml1 = g_ML[1][row];
        float4 o0 = *(const float4*)&g_Opart[0][(size_t)row * D_ + dcol];
        float4 o1 = *(const float4*)&g_Opart[1][(size_t)row * D_ + dcol];

        float m = fmaxf(ml0.x, ml1.x);
        float a0 = __expf(ml0.x - m);
        float a1 = __expf(ml1.x - m);
        float inv = 1.0f / fmaf(ml0.y, a0, ml1.y * a1);

        float4 r;
        r.x = fmaf(o0.x, a0, o1.x * a1) * inv;
        r.y = fmaf(o0.y, a0, o1.y * a1) * inv;
        r.z = fmaf(o0.z, a0, o1.z * a1) * inv;
        r.w = fmaf(o0.w, a0, o1.w * a1) * inv;
        *(float4*)(Og + (size_t)row * D_ + dcol) = r;
    }
}

// ---------------------------------------------------------------------------
// kernel_launch
// Input order: Q, K, V, distance_matrix, energy_matrix, mask,
//              mu_D, sigma_D, b_D, mu_E, sigma_E, b_E, W1, b1, W2, b2
// ---------------------------------------------------------------------------
extern "C" void kernel_launch(void* const* d_in, const int* in_sizes, int n_in,
                              void* d_out, int out_size) {
    const float* Q  = (const float*)d_in[0];
    const float* K  = (const float*)d_in[1];
    const float* V  = (const float*)d_in[2];
    const float* DM = (const float*)d_in[3];
    const float* EM = (const float*)d_in[4];
    const int*   MK = (const int*)d_in[5];
    const float* muD = (const float*)d_in[6];
    const float* sgD = (const float*)d_in[7];
    const float* bD  = (const float*)d_in[8];
    const float* muE = (const float*)d_in[9];
    const float* sgE = (const float*)d_in[10];
    const float* bE  = (const float*)d_in[11];
    const float* W1  = (const float*)d_in[12];
    const float* b1  = (const float*)d_in[13];
    const float* W2  = (const float*)d_in[14];
    const float* b2  = (const float*)d_in[15];
    float* Og = (float*)d_out;

    const int smem_bytes = 2 * LUTN * (int)sizeof(float2)
                         + 8 * BI * QS * (int)sizeof(__nv_bfloat16)
                         + 4 * BI * (int)sizeof(float);

    cudaFuncSetAttribute(attn_partial_kernel, cudaFuncAttributeMaxDynamicSharedMemorySize, smem_bytes);

    int nev = 2 * (LUTN + 1);
    build_vals_kernel<<<(nev + 255) / 256, 256>>>(muD, sgD, bD, muE, sgE, bE, W1, b1, W2, b2);
    build_slopes_kernel<<<(LUTN + 255) / 256, 256>>>();

    dim3 grid(S_ / BI, H_, NSPLIT);
    attn_partial_kernel<<<grid, NT, smem_bytes>>>(Q, K, V, DM, EM, MK);

    combine_kernel<<<(COMB_N / 2 + 255) / 256, 256>>>(Og);
}